// round 3
// baseline (speedup 1.0000x reference)
#include <cuda_runtime.h>
#include <cuda_bf16.h>

#define NN 50000
#define EE 800000
#define EPSQ 1e-16f

// ---------------- scratch (static device globals; no allocation) ----------------
__device__ float g_h1  [NN * 128];   // layer1 linear output [N,2,64]
__device__ float g_a1s [NN * 2];
__device__ float g_a1d [NN * 2];
__device__ float g_agg1[NN * 128];
__device__ float g_den1[NN * 2];
__device__ float g_hmid[NN * 128];   // elu(layer1 out) -> layer2 input
__device__ float g_h2  [NN * 64];
__device__ float g_a2s [NN];
__device__ float g_a2d [NN];
__device__ float g_agg2[NN * 64];
__device__ float g_den2[NN];
__device__ int   g_src [EE];
__device__ int   g_dst [EE];
__device__ int   g_e64;              // 1 if edge_index is int64, 0 if int32

__device__ __forceinline__ float lrelu(float x) { return x > 0.f ? x : 0.2f * x; }
__device__ __forceinline__ float elu1(float x)  { return x > 0.f ? x : expm1f(x); }

// ---------------- edge dtype detect + convert ----------------
// Interpreting the first E entries as int64 is in-bounds for BOTH dtypes:
// an int64 read of element e (e < E) touches bytes [8e, 8e+8), and the buffer
// is 8E bytes in either interpretation (2E int32 = 8E bytes; 2E int64 = 16E).
// If the data is really int32, an int64 lane holds two packed int32 node ids,
// so the 64-bit value is >= 2^32 (any nonzero high word) or a small id with a
// zero high word; random ids in [0, 50000) make all-256 samples passing the
// [0, n) test astronomically unlikely unless the dtype truly is int64.
__global__ void detect_kernel(const void* ei, int E, int n) {
    __shared__ int ok;
    if (threadIdx.x == 0) ok = 1;
    __syncthreads();
    int stride = E > 256 ? E / 256 : 1;
    long long idx = (long long)threadIdx.x * stride;
    if (idx < E) {
        long long v = ((const long long*)ei)[idx];
        if (v < 0 || v >= n) ok = 0;   // benign race: all writers store 0
    }
    __syncthreads();
    if (threadIdx.x == 0) g_e64 = ok;
}

__global__ void convert_kernel(const void* ei, int E) {
    int e = blockIdx.x * blockDim.x + threadIdx.x;
    if (e >= E) return;
    int is64 = g_e64;                  // uniform across the grid
    if (is64) {
        const long long* p = (const long long*)ei;
        g_src[e] = (int)p[e];
        g_dst[e] = (int)p[E + e];
    } else {
        const int* p = (const int*)ei;
        g_src[e] = p[e];
        g_dst[e] = p[E + e];
    }
}

// ---------------- generic fp32 SGEMM body: C[n,M] = A[n,K] @ B[K,M] ----------------
// 64x64 tile, BK=16, 256 threads, 4x4 per thread
__device__ __forceinline__ void sgemm_body(const float* __restrict__ A,
                                           const float* __restrict__ B,
                                           float* __restrict__ C, int n, int K, int M) {
    __shared__ float As[64][17];
    __shared__ float Bs[16][64];
    int tid = threadIdx.x;
    int tx = tid & 15, ty = tid >> 4;
    int rowBase = blockIdx.y * 64;
    int colBase = blockIdx.x * 64;
    float acc[4][4] = {};
    for (int k0 = 0; k0 < K; k0 += 16) {
        {   // load A tile (64x16)
            int r  = tid >> 2;
            int c4 = (tid & 3) * 4;
            float4 v = make_float4(0.f, 0.f, 0.f, 0.f);
            if (rowBase + r < n)
                v = *(const float4*)&A[(size_t)(rowBase + r) * K + k0 + c4];
            As[r][c4] = v.x; As[r][c4 + 1] = v.y; As[r][c4 + 2] = v.z; As[r][c4 + 3] = v.w;
        }
        {   // load B tile (16x64)
            int r  = tid >> 4;
            int c4 = (tid & 15) * 4;
            *(float4*)&Bs[r][c4] = *(const float4*)&B[(size_t)(k0 + r) * M + colBase + c4];
        }
        __syncthreads();
        #pragma unroll
        for (int kk = 0; kk < 16; kk++) {
            float a[4], b[4];
            #pragma unroll
            for (int i = 0; i < 4; i++) a[i] = As[ty * 4 + i][kk];
            #pragma unroll
            for (int j = 0; j < 4; j++) b[j] = Bs[kk][tx * 4 + j];
            #pragma unroll
            for (int i = 0; i < 4; i++)
                #pragma unroll
                for (int j = 0; j < 4; j++)
                    acc[i][j] += a[i] * b[j];
        }
        __syncthreads();
    }
    #pragma unroll
    for (int i = 0; i < 4; i++) {
        int r = rowBase + ty * 4 + i;
        if (r < n) {
            #pragma unroll
            for (int j = 0; j < 4; j++)
                C[(size_t)r * M + colBase + tx * 4 + j] = acc[i][j];
        }
    }
}

// wrappers bind C (and A for layer2) to device symbols in device code — no
// cudaGetSymbolAddress needed on the host.
__global__ void sgemm1_kernel(const float* __restrict__ A, const float* __restrict__ B, int n) {
    sgemm_body(A, B, g_h1, n, 128, 128);
}
__global__ void sgemm2_kernel(const float* __restrict__ B, int n) {
    sgemm_body(g_hmid, B, g_h2, n, 128, 64);
}

// ---------------- layer1 node prep: attention logits + self-loop init ----------------
// warp per node; 128 channels (2 heads x 64)
__global__ void prep1_kernel(const float* __restrict__ att_s, const float* __restrict__ att_d, int n) {
    int w = (blockIdx.x * blockDim.x + threadIdx.x) >> 5;
    if (w >= n) return;
    int lane = threadIdx.x & 31;
    int c0 = lane * 4;
    float4 h  = *(const float4*)&g_h1[(size_t)w * 128 + c0];
    float4 s4 = *(const float4*)&att_s[c0];
    float4 d4 = *(const float4*)&att_d[c0];
    float ps = h.x * s4.x + h.y * s4.y + h.z * s4.z + h.w * s4.w;
    float pd = h.x * d4.x + h.y * d4.y + h.z * d4.z + h.w * d4.w;
    // reduce within each 16-lane half (lanes 0-15 = head0, 16-31 = head1)
    #pragma unroll
    for (int off = 8; off >= 1; off >>= 1) {
        ps += __shfl_down_sync(0xffffffffu, ps, off);
        pd += __shfl_down_sync(0xffffffffu, pd, off);
    }
    float s0 = __shfl_sync(0xffffffffu, ps, 0);
    float s1 = __shfl_sync(0xffffffffu, ps, 16);
    float d0 = __shfl_sync(0xffffffffu, pd, 0);
    float d1 = __shfl_sync(0xffffffffu, pd, 16);
    float w0 = __expf(lrelu(s0 + d0));
    float w1 = __expf(lrelu(s1 + d1));
    float ww = (c0 < 64) ? w0 : w1;
    *(float4*)&g_agg1[(size_t)w * 128 + c0] =
        make_float4(h.x * ww, h.y * ww, h.z * ww, h.w * ww);
    if (lane == 0) {
        g_a1s[2 * w] = s0; g_a1s[2 * w + 1] = s1;
        g_a1d[2 * w] = d0; g_a1d[2 * w + 1] = d1;
        g_den1[2 * w] = w0; g_den1[2 * w + 1] = w1;
    }
}

// ---------------- layer1 edge scatter (warp per edge) ----------------
__global__ void edge1_kernel(int E) {
    int e = (blockIdx.x * blockDim.x + threadIdx.x) >> 5;
    if (e >= E) return;
    int lane = threadIdx.x & 31;
    int s = g_src[e];
    int d = g_dst[e];
    float w0 = __expf(lrelu(g_a1s[2 * s]     + g_a1d[2 * d]));
    float w1 = __expf(lrelu(g_a1s[2 * s + 1] + g_a1d[2 * d + 1]));
    int c0 = lane * 4;
    float4 h = *(const float4*)&g_h1[(size_t)s * 128 + c0];
    float ww = (c0 < 64) ? w0 : w1;
    float* dst = &g_agg1[(size_t)d * 128 + c0];
    atomicAdd(dst,     h.x * ww);
    atomicAdd(dst + 1, h.y * ww);
    atomicAdd(dst + 2, h.z * ww);
    atomicAdd(dst + 3, h.w * ww);
    if (lane == 0) atomicAdd(&g_den1[2 * d], w0);
    if (lane == 1) atomicAdd(&g_den1[2 * d + 1], w1);
}

// ---------------- layer1 finalize: normalize + bias + elu -> hmid ----------------
__global__ void mid1_kernel(const float* __restrict__ b1, int n) {
    int id = blockIdx.x * blockDim.x + threadIdx.x;   // one float4 each
    if (id >= n * 32) return;
    int base = id * 4;
    int node = id >> 5;
    int c    = base & 127;
    int head = (c >> 6) & 1;
    float4 a = *(const float4*)&g_agg1[base];
    float r  = 1.0f / (g_den1[2 * node + head] + EPSQ);
    float4 o;
    o.x = elu1(a.x * r + b1[c]);
    o.y = elu1(a.y * r + b1[c + 1]);
    o.z = elu1(a.z * r + b1[c + 2]);
    o.w = elu1(a.w * r + b1[c + 3]);
    *(float4*)&g_hmid[base] = o;
}

// ---------------- layer2 node prep (1 head, 64 ch; warp per node) ----------------
__global__ void prep2_kernel(const float* __restrict__ att_s, const float* __restrict__ att_d, int n) {
    int w = (blockIdx.x * blockDim.x + threadIdx.x) >> 5;
    if (w >= n) return;
    int lane = threadIdx.x & 31;
    int c0 = lane * 2;
    float2 h  = *(const float2*)&g_h2[(size_t)w * 64 + c0];
    float ps = h.x * att_s[c0] + h.y * att_s[c0 + 1];
    float pd = h.x * att_d[c0] + h.y * att_d[c0 + 1];
    #pragma unroll
    for (int off = 16; off >= 1; off >>= 1) {
        ps += __shfl_down_sync(0xffffffffu, ps, off);
        pd += __shfl_down_sync(0xffffffffu, pd, off);
    }
    float s0 = __shfl_sync(0xffffffffu, ps, 0);
    float d0 = __shfl_sync(0xffffffffu, pd, 0);
    float w0 = __expf(lrelu(s0 + d0));
    *(float2*)&g_agg2[(size_t)w * 64 + c0] = make_float2(h.x * w0, h.y * w0);
    if (lane == 0) {
        g_a2s[w] = s0; g_a2d[w] = d0; g_den2[w] = w0;
    }
}

// ---------------- layer2 edge scatter (warp per edge) ----------------
__global__ void edge2_kernel(int E) {
    int e = (blockIdx.x * blockDim.x + threadIdx.x) >> 5;
    if (e >= E) return;
    int lane = threadIdx.x & 31;
    int s = g_src[e];
    int d = g_dst[e];
    float w0 = __expf(lrelu(g_a2s[s] + g_a2d[d]));
    int c0 = lane * 2;
    float2 h = *(const float2*)&g_h2[(size_t)s * 64 + c0];
    float* dst = &g_agg2[(size_t)d * 64 + c0];
    atomicAdd(dst,     h.x * w0);
    atomicAdd(dst + 1, h.y * w0);
    if (lane == 0) atomicAdd(&g_den2[d], w0);
}

// ---------------- final: normalize+elu, @ lin_w + lin_b, sigmoid ----------------
// 16 nodes per 256-thread block; 16 threads per node
__global__ void final_kernel(const float* __restrict__ b2, const float* __restrict__ lin_w,
                             const float* __restrict__ lin_b, float* __restrict__ out, int n) {
    __shared__ float sw[64 * 16];
    __shared__ float st[16][66];
    int tid = threadIdx.x;
    int nb = blockIdx.x * 16;
    #pragma unroll
    for (int i = 0; i < 4; i++) sw[tid + 256 * i] = lin_w[tid + 256 * i];
    #pragma unroll
    for (int i = 0; i < 4; i++) {
        int id = tid + 256 * i;          // 0..1023
        int g = id >> 6;
        int c = id & 63;
        int node = nb + g;
        float v = 0.f;
        if (node < n) {
            v = g_agg2[(size_t)node * 64 + c] / (g_den2[node] + EPSQ) + b2[c];
            v = elu1(v);
        }
        st[g][c] = v;
    }
    __syncthreads();
    int g = tid >> 4;
    int o = tid & 15;
    int node = nb + g;
    if (node >= n) return;
    float acc = lin_b[o];
    #pragma unroll
    for (int c = 0; c < 64; c++)
        acc += st[g][c] * sw[c * 16 + o];
    out[(size_t)node * 16 + o] = 1.0f / (1.0f + __expf(-acc));
}

// ---------------- launcher ----------------
extern "C" void kernel_launch(void* const* d_in, const int* in_sizes, int n_in,
                              void* d_out, int out_size) {
    const float* x        = (const float*)d_in[0];
    const void*  ei       = d_in[1];
    const float* W1       = (const float*)d_in[2];
    const float* att_src1 = (const float*)d_in[3];
    const float* att_dst1 = (const float*)d_in[4];
    const float* b1       = (const float*)d_in[5];
    const float* W2       = (const float*)d_in[6];
    const float* att_src2 = (const float*)d_in[7];
    const float* att_dst2 = (const float*)d_in[8];
    const float* b2       = (const float*)d_in[9];
    const float* lin_w    = (const float*)d_in[10];
    const float* lin_b    = (const float*)d_in[11];
    float*       out      = (float*)d_out;

    int n = in_sizes[0] / 128;        // 50000
    int E = in_sizes[1] / 2;          // 800000

    // edge dtype detect + int32 conversion
    detect_kernel<<<1, 256>>>(ei, E, n);
    convert_kernel<<<(E + 255) / 256, 256>>>(ei, E);

    // layer 1
    sgemm1_kernel<<<dim3(2, (n + 63) / 64), 256>>>(x, W1, n);
    prep1_kernel<<<(n + 7) / 8, 256>>>(att_src1, att_dst1, n);
    edge1_kernel<<<(E + 7) / 8, 256>>>(E);
    mid1_kernel<<<(n * 32 + 255) / 256, 256>>>(b1, n);
    // layer 2
    sgemm2_kernel<<<dim3(1, (n + 63) / 64), 256>>>(W2, n);
    prep2_kernel<<<(n + 7) / 8, 256>>>(att_src2, att_dst2, n);
    edge2_kernel<<<(E + 7) / 8, 256>>>(E);
    // head
    final_kernel<<<(n + 15) / 16, 256>>>(b2, lin_w, lin_b, out, n);
}

// round 4
// speedup vs baseline: 1.5628x; 1.5628x over previous
#include <cuda_runtime.h>
#include <cuda_bf16.h>

#define NN 50000
#define EE 800000
#define EPSQ 1e-16f

// ---------------- scratch (static device globals; no allocation) ----------------
__device__ float g_h1  [NN * 128];   // layer1 linear output [N,2,64]
__device__ float g_a1s [NN * 2];
__device__ float g_a1d [NN * 2];
__device__ float g_hmid[NN * 128];   // layer1 final (normalized+bias+elu) -> layer2 input
__device__ float g_h2  [NN * 64];
__device__ float g_a2s [NN];
__device__ float g_a2d [NN];
__device__ float g_hout[NN * 64];    // layer2 final (normalized+bias+elu)
__device__ int   g_src [EE];
__device__ int   g_dst [EE];
__device__ int   g_deg [NN];
__device__ int   g_ptr [NN + 1];
__device__ int   g_pos [NN];
__device__ int   g_ssrc[EE];         // src ids sorted by dst (CSR payload)
__device__ int   g_e64;              // 1 if edge_index is int64, 0 if int32

__device__ __forceinline__ float lrelu(float x) { return x > 0.f ? x : 0.2f * x; }
__device__ __forceinline__ float elu1(float x)  { return x > 0.f ? x : expm1f(x); }

// ---------------- edge dtype detect ----------------
// Reading entry e<E as int64 is in-bounds for both dtypes (buffer >= 8E bytes).
__global__ void detect_kernel(const void* ei, int E, int n) {
    __shared__ int ok;
    if (threadIdx.x == 0) ok = 1;
    __syncthreads();
    int stride = E > 256 ? E / 256 : 1;
    long long idx = (long long)threadIdx.x * stride;
    if (idx < E) {
        long long v = ((const long long*)ei)[idx];
        if (v < 0 || v >= n) ok = 0;   // benign race: all writers store 0
    }
    __syncthreads();
    if (threadIdx.x == 0) g_e64 = ok;
}

__global__ void zero_kernel(int n) {
    int i = blockIdx.x * blockDim.x + threadIdx.x;
    if (i < n) g_deg[i] = 0;
}

// ---------------- convert + degree histogram ----------------
__global__ void convert_kernel(const void* ei, int E) {
    int e = blockIdx.x * blockDim.x + threadIdx.x;
    if (e >= E) return;
    int s, d;
    if (g_e64) {
        const long long* p = (const long long*)ei;
        s = (int)p[e];
        d = (int)p[E + e];
    } else {
        const int* p = (const int*)ei;
        s = p[e];
        d = p[E + e];
    }
    g_src[e] = s;
    g_dst[e] = d;
    atomicAdd(&g_deg[d], 1);
}

// ---------------- single-block exclusive scan of g_deg -> g_ptr / g_pos ----------------
__global__ void scan_kernel(int n) {
    const int T = 1024;
    int tid = threadIdx.x;
    int chunk = (n + T - 1) / T;
    int b = tid * chunk;
    int e = min(b + chunk, n);
    int s = 0;
    for (int i = b; i < e; i++) s += g_deg[i];
    // block-wide exclusive scan of per-thread sums
    int lane = tid & 31, wid = tid >> 5;
    int v = s;
    #pragma unroll
    for (int off = 1; off < 32; off <<= 1) {
        int t = __shfl_up_sync(0xffffffffu, v, off);
        if (lane >= off) v += t;
    }
    __shared__ int ws[32];
    if (lane == 31) ws[wid] = v;
    __syncthreads();
    if (wid == 0) {
        int u = ws[lane];
        #pragma unroll
        for (int off = 1; off < 32; off <<= 1) {
            int t = __shfl_up_sync(0xffffffffu, u, off);
            if (lane >= off) u += t;
        }
        ws[lane] = u;
    }
    __syncthreads();
    int run = v - s + (wid > 0 ? ws[wid - 1] : 0);
    for (int i = b; i < e; i++) {
        g_ptr[i] = run;
        g_pos[i] = run;
        run += g_deg[i];
    }
    if (b < n && e == n) g_ptr[n] = run;   // unique last active thread
}

// ---------------- scatter src into dst-sorted order ----------------
__global__ void scatter_kernel(int E) {
    int e = blockIdx.x * blockDim.x + threadIdx.x;
    if (e >= E) return;
    int d = g_dst[e];
    int p = atomicAdd(&g_pos[d], 1);
    g_ssrc[p] = g_src[e];
}

// ---------------- generic fp32 SGEMM body: C[n,M] = A[n,K] @ B[K,M] ----------------
__device__ __forceinline__ void sgemm_body(const float* __restrict__ A,
                                           const float* __restrict__ B,
                                           float* __restrict__ C, int n, int K, int M) {
    __shared__ float As[64][17];
    __shared__ float Bs[16][64];
    int tid = threadIdx.x;
    int tx = tid & 15, ty = tid >> 4;
    int rowBase = blockIdx.y * 64;
    int colBase = blockIdx.x * 64;
    float acc[4][4] = {};
    for (int k0 = 0; k0 < K; k0 += 16) {
        {
            int r  = tid >> 2;
            int c4 = (tid & 3) * 4;
            float4 v = make_float4(0.f, 0.f, 0.f, 0.f);
            if (rowBase + r < n)
                v = *(const float4*)&A[(size_t)(rowBase + r) * K + k0 + c4];
            As[r][c4] = v.x; As[r][c4 + 1] = v.y; As[r][c4 + 2] = v.z; As[r][c4 + 3] = v.w;
        }
        {
            int r  = tid >> 4;
            int c4 = (tid & 15) * 4;
            *(float4*)&Bs[r][c4] = *(const float4*)&B[(size_t)(k0 + r) * M + colBase + c4];
        }
        __syncthreads();
        #pragma unroll
        for (int kk = 0; kk < 16; kk++) {
            float a[4], bb[4];
            #pragma unroll
            for (int i = 0; i < 4; i++) a[i] = As[ty * 4 + i][kk];
            #pragma unroll
            for (int j = 0; j < 4; j++) bb[j] = Bs[kk][tx * 4 + j];
            #pragma unroll
            for (int i = 0; i < 4; i++)
                #pragma unroll
                for (int j = 0; j < 4; j++)
                    acc[i][j] += a[i] * bb[j];
        }
        __syncthreads();
    }
    #pragma unroll
    for (int i = 0; i < 4; i++) {
        int r = rowBase + ty * 4 + i;
        if (r < n) {
            #pragma unroll
            for (int j = 0; j < 4; j++)
                C[(size_t)r * M + colBase + tx * 4 + j] = acc[i][j];
        }
    }
}

__global__ void sgemm1_kernel(const float* __restrict__ A, const float* __restrict__ B, int n) {
    sgemm_body(A, B, g_h1, n, 128, 128);
}
__global__ void sgemm2_kernel(const float* __restrict__ B, int n) {
    sgemm_body(g_hmid, B, g_h2, n, 128, 64);
}

// ---------------- layer1 node prep: attention logits only ----------------
__global__ void prep1_kernel(const float* __restrict__ att_s, const float* __restrict__ att_d, int n) {
    int w = (blockIdx.x * blockDim.x + threadIdx.x) >> 5;
    if (w >= n) return;
    int lane = threadIdx.x & 31;
    int c0 = lane * 4;
    float4 h  = *(const float4*)&g_h1[(size_t)w * 128 + c0];
    float4 s4 = *(const float4*)&att_s[c0];
    float4 d4 = *(const float4*)&att_d[c0];
    float ps = h.x * s4.x + h.y * s4.y + h.z * s4.z + h.w * s4.w;
    float pd = h.x * d4.x + h.y * d4.y + h.z * d4.z + h.w * d4.w;
    #pragma unroll
    for (int off = 8; off >= 1; off >>= 1) {   // reduce each 16-lane half
        ps += __shfl_down_sync(0xffffffffu, ps, off);
        pd += __shfl_down_sync(0xffffffffu, pd, off);
    }
    if (lane == 0)  { g_a1s[2 * w]     = ps; g_a1d[2 * w]     = pd; }
    if (lane == 16) { g_a1s[2 * w + 1] = ps; g_a1d[2 * w + 1] = pd; }
}

// ---------------- layer1 gather: softmax-weighted aggregation + bias + elu ----------------
// warp per node; no atomics
__global__ void gather1_kernel(const float* __restrict__ b1, int n) {
    int w = (blockIdx.x * blockDim.x + threadIdx.x) >> 5;
    if (w >= n) return;
    int lane = threadIdx.x & 31;
    int c0 = lane * 4;
    float a1d0 = g_a1d[2 * w], a1d1 = g_a1d[2 * w + 1];
    // self loop
    float ws0 = __expf(lrelu(g_a1s[2 * w]     + a1d0));
    float ws1 = __expf(lrelu(g_a1s[2 * w + 1] + a1d1));
    float4 hs = *(const float4*)&g_h1[(size_t)w * 128 + c0];
    float wws = (c0 < 64) ? ws0 : ws1;
    float4 acc = make_float4(hs.x * wws, hs.y * wws, hs.z * wws, hs.w * wws);
    float den0 = (lane == 0) ? ws0 : 0.f;
    float den1 = (lane == 0) ? ws1 : 0.f;
    int start = g_ptr[w], end = g_ptr[w + 1];
    for (int base = start; base < end; base += 32) {
        int j = base + lane;
        int s = 0; float e0 = 0.f, e1 = 0.f;
        if (j < end) {
            s = g_ssrc[j];
            float2 as = *(const float2*)&g_a1s[2 * s];
            e0 = __expf(lrelu(as.x + a1d0));
            e1 = __expf(lrelu(as.y + a1d1));
        }
        den0 += e0; den1 += e1;
        int m = min(32, end - base);
        for (int k = 0; k < m; k++) {
            int   sk  = __shfl_sync(0xffffffffu, s, k);
            float w0k = __shfl_sync(0xffffffffu, e0, k);
            float w1k = __shfl_sync(0xffffffffu, e1, k);
            float4 h = *(const float4*)&g_h1[(size_t)sk * 128 + c0];
            float ww = (c0 < 64) ? w0k : w1k;
            acc.x += h.x * ww; acc.y += h.y * ww; acc.z += h.z * ww; acc.w += h.w * ww;
        }
    }
    #pragma unroll
    for (int off = 16; off >= 1; off >>= 1) {
        den0 += __shfl_xor_sync(0xffffffffu, den0, off);
        den1 += __shfl_xor_sync(0xffffffffu, den1, off);
    }
    float r = 1.0f / (((c0 < 64) ? den0 : den1) + EPSQ);
    float4 o;
    o.x = elu1(acc.x * r + b1[c0]);
    o.y = elu1(acc.y * r + b1[c0 + 1]);
    o.z = elu1(acc.z * r + b1[c0 + 2]);
    o.w = elu1(acc.w * r + b1[c0 + 3]);
    *(float4*)&g_hmid[(size_t)w * 128 + c0] = o;
}

// ---------------- layer2 node prep ----------------
__global__ void prep2_kernel(const float* __restrict__ att_s, const float* __restrict__ att_d, int n) {
    int w = (blockIdx.x * blockDim.x + threadIdx.x) >> 5;
    if (w >= n) return;
    int lane = threadIdx.x & 31;
    int c0 = lane * 2;
    float2 h  = *(const float2*)&g_h2[(size_t)w * 64 + c0];
    float ps = h.x * att_s[c0] + h.y * att_s[c0 + 1];
    float pd = h.x * att_d[c0] + h.y * att_d[c0 + 1];
    #pragma unroll
    for (int off = 16; off >= 1; off >>= 1) {
        ps += __shfl_down_sync(0xffffffffu, ps, off);
        pd += __shfl_down_sync(0xffffffffu, pd, off);
    }
    if (lane == 0) { g_a2s[w] = ps; g_a2d[w] = pd; }
}

// ---------------- layer2 gather + bias + elu ----------------
__global__ void gather2_kernel(const float* __restrict__ b2, int n) {
    int w = (blockIdx.x * blockDim.x + threadIdx.x) >> 5;
    if (w >= n) return;
    int lane = threadIdx.x & 31;
    int c0 = lane * 2;
    float a2d = g_a2d[w];
    float ws0 = __expf(lrelu(g_a2s[w] + a2d));
    float2 hs = *(const float2*)&g_h2[(size_t)w * 64 + c0];
    float2 acc = make_float2(hs.x * ws0, hs.y * ws0);
    float den = (lane == 0) ? ws0 : 0.f;
    int start = g_ptr[w], end = g_ptr[w + 1];
    for (int base = start; base < end; base += 32) {
        int j = base + lane;
        int s = 0; float e0 = 0.f;
        if (j < end) {
            s = g_ssrc[j];
            e0 = __expf(lrelu(g_a2s[s] + a2d));
        }
        den += e0;
        int m = min(32, end - base);
        for (int k = 0; k < m; k++) {
            int   sk  = __shfl_sync(0xffffffffu, s, k);
            float w0k = __shfl_sync(0xffffffffu, e0, k);
            float2 h = *(const float2*)&g_h2[(size_t)sk * 64 + c0];
            acc.x += h.x * w0k; acc.y += h.y * w0k;
        }
    }
    #pragma unroll
    for (int off = 16; off >= 1; off >>= 1)
        den += __shfl_xor_sync(0xffffffffu, den, off);
    float r = 1.0f / (den + EPSQ);
    float2 o;
    o.x = elu1(acc.x * r + b2[c0]);
    o.y = elu1(acc.y * r + b2[c0 + 1]);
    *(float2*)&g_hout[(size_t)w * 64 + c0] = o;
}

// ---------------- final: @ lin_w + lin_b, sigmoid ----------------
__global__ void final_kernel(const float* __restrict__ lin_w, const float* __restrict__ lin_b,
                             float* __restrict__ out, int n) {
    __shared__ float sw[64 * 16];
    __shared__ float st[16][66];
    int tid = threadIdx.x;
    int nb = blockIdx.x * 16;
    #pragma unroll
    for (int i = 0; i < 4; i++) sw[tid + 256 * i] = lin_w[tid + 256 * i];
    #pragma unroll
    for (int i = 0; i < 4; i++) {
        int id = tid + 256 * i;          // 0..1023
        int g = id >> 6;
        int c = id & 63;
        int node = nb + g;
        st[g][c] = (node < n) ? g_hout[(size_t)node * 64 + c] : 0.f;
    }
    __syncthreads();
    int g = tid >> 4;
    int o = tid & 15;
    int node = nb + g;
    if (node >= n) return;
    float acc = lin_b[o];
    #pragma unroll
    for (int c = 0; c < 64; c++)
        acc += st[g][c] * sw[c * 16 + o];
    out[(size_t)node * 16 + o] = 1.0f / (1.0f + __expf(-acc));
}

// ---------------- launcher ----------------
extern "C" void kernel_launch(void* const* d_in, const int* in_sizes, int n_in,
                              void* d_out, int out_size) {
    const float* x        = (const float*)d_in[0];
    const void*  ei       = d_in[1];
    const float* W1       = (const float*)d_in[2];
    const float* att_src1 = (const float*)d_in[3];
    const float* att_dst1 = (const float*)d_in[4];
    const float* b1       = (const float*)d_in[5];
    const float* W2       = (const float*)d_in[6];
    const float* att_src2 = (const float*)d_in[7];
    const float* att_dst2 = (const float*)d_in[8];
    const float* b2       = (const float*)d_in[9];
    const float* lin_w    = (const float*)d_in[10];
    const float* lin_b    = (const float*)d_in[11];
    float*       out      = (float*)d_out;

    int n = in_sizes[0] / 128;        // 50000
    int E = in_sizes[1] / 2;          // 800000

    // CSR build (shared by both layers)
    detect_kernel <<<1, 256>>>(ei, E, n);
    zero_kernel   <<<(n + 255) / 256, 256>>>(n);
    convert_kernel<<<(E + 255) / 256, 256>>>(ei, E);
    scan_kernel   <<<1, 1024>>>(n);
    scatter_kernel<<<(E + 255) / 256, 256>>>(E);

    // layer 1
    sgemm1_kernel <<<dim3(2, (n + 63) / 64), 256>>>(x, W1, n);
    prep1_kernel  <<<(n + 7) / 8, 256>>>(att_src1, att_dst1, n);
    gather1_kernel<<<(n + 7) / 8, 256>>>(b1, n);
    // layer 2
    sgemm2_kernel <<<dim3(1, (n + 63) / 64), 256>>>(W2, n);
    prep2_kernel  <<<(n + 7) / 8, 256>>>(att_src2, att_dst2, n);
    gather2_kernel<<<(n + 7) / 8, 256>>>(b2, n);
    // head
    final_kernel  <<<(n + 15) / 16, 256>>>(lin_w, lin_b, out, n);
}

// round 5
// speedup vs baseline: 2.0519x; 1.3130x over previous
#include <cuda_runtime.h>
#include <cuda_bf16.h>

#define NN 50000
#define EE 800000
#define EPSQ 1e-16f

// ---------------- scratch (static device globals; no allocation) ----------------
__device__ float g_h1  [NN * 128];   // layer1 linear output [N,2,64]
__device__ float g_a1s [NN * 2];
__device__ float g_a1d [NN * 2];
__device__ float g_hmid[NN * 128];   // layer1 final (normalized+bias+elu) -> layer2 input
__device__ float g_h2  [NN * 64];
__device__ float g_a2s [NN];
__device__ float g_a2d [NN];
__device__ float g_hout[NN * 64];    // layer2 final (normalized+bias+elu)
__device__ int   g_src [EE];
__device__ int   g_dst [EE];
__device__ int   g_deg [NN + 4];     // +pad so int4 tail loads stay in-bounds
__device__ int   g_ptr [NN + 8];
__device__ int   g_pos [NN + 8];
__device__ int   g_ssrc[EE];         // src ids sorted by dst (CSR payload)
__device__ int   g_bsum[64];
__device__ int   g_boff[64];
__device__ int   g_e64;              // 1 if edge_index is int64, 0 if int32

__device__ __forceinline__ float lrelu(float x) { return x > 0.f ? x : 0.2f * x; }
__device__ __forceinline__ float elu1(float x)  { return x > 0.f ? x : expm1f(x); }

// ---------------- edge dtype detect ----------------
// Reading entry e<E as int64 is in-bounds for both dtypes (buffer >= 8E bytes).
__global__ void detect_kernel(const void* ei, int E, int n) {
    __shared__ int ok;
    if (threadIdx.x == 0) ok = 1;
    __syncthreads();
    int stride = E > 256 ? E / 256 : 1;
    long long idx = (long long)threadIdx.x * stride;
    if (idx < E) {
        long long v = ((const long long*)ei)[idx];
        if (v < 0 || v >= n) ok = 0;   // benign race: all writers store 0
    }
    __syncthreads();
    if (threadIdx.x == 0) g_e64 = ok;
}

__global__ void zero_kernel(int n) {
    int i = blockIdx.x * blockDim.x + threadIdx.x;
    if (i < n + 4) g_deg[i] = 0;
}

// ---------------- convert + degree histogram ----------------
__global__ void convert_kernel(const void* ei, int E) {
    int e = blockIdx.x * blockDim.x + threadIdx.x;
    if (e >= E) return;
    int s, d;
    if (g_e64) {
        const long long* p = (const long long*)ei;
        s = (int)p[e];
        d = (int)p[E + e];
    } else {
        const int* p = (const int*)ei;
        s = p[e];
        d = p[E + e];
    }
    g_src[e] = s;
    g_dst[e] = d;
    atomicAdd(&g_deg[d], 1);
}

// ---------------- 3-phase parallel exclusive scan: g_deg -> g_ptr / g_pos ----------------
// Phase A: per-block (1024-elem tile) reduction -> g_bsum
__global__ void scanA_kernel(int n) {
    int b = blockIdx.x;
    int base = b * 1024 + threadIdx.x * 4;
    int s = 0;
    if (base < n) {                        // g_deg padded: int4 always in-bounds
        int4 v = *(const int4*)&g_deg[base];
        // zero-out past-end lanes (pad region is zeroed anyway, but be exact)
        s = v.x + ((base + 1 < n) ? v.y : 0) + ((base + 2 < n) ? v.z : 0) + ((base + 3 < n) ? v.w : 0);
    }
    int lane = threadIdx.x & 31, wid = threadIdx.x >> 5;
    #pragma unroll
    for (int off = 16; off >= 1; off >>= 1) s += __shfl_xor_sync(0xffffffffu, s, off);
    __shared__ int ws[8];
    if (lane == 0) ws[wid] = s;
    __syncthreads();
    if (threadIdx.x == 0) {
        int t = 0;
        #pragma unroll
        for (int i = 0; i < 8; i++) t += ws[i];
        g_bsum[b] = t;
    }
}

// Phase B: exclusive scan of <=64 block sums (1 block, 64 threads)
__global__ void scanB_kernel(int nb) {
    int tid = threadIdx.x;
    int lane = tid & 31, w = tid >> 5;
    int v = (tid < nb) ? g_bsum[tid] : 0;
    int inc = v;
    #pragma unroll
    for (int off = 1; off < 32; off <<= 1) {
        int t = __shfl_up_sync(0xffffffffu, inc, off);
        if (lane >= off) inc += t;
    }
    __shared__ int wt[2];
    if (lane == 31) wt[w] = inc;
    __syncthreads();
    if (w == 1) inc += wt[0];
    g_boff[tid] = inc - v;   // exclusive
}

// Phase C: in-tile scan + block offset; write g_ptr and g_pos
__global__ void scanC_kernel(int n) {
    int b = blockIdx.x;
    int idx0 = b * 1024 + threadIdx.x * 4;
    int d0 = 0, d1 = 0, d2 = 0, d3 = 0;
    if (idx0 < n) {
        int4 v = *(const int4*)&g_deg[idx0];
        d0 = v.x;
        d1 = (idx0 + 1 < n) ? v.y : 0;
        d2 = (idx0 + 2 < n) ? v.z : 0;
        d3 = (idx0 + 3 < n) ? v.w : 0;
    }
    int tsum = d0 + d1 + d2 + d3;
    int lane = threadIdx.x & 31, wid = threadIdx.x >> 5;
    int inc = tsum;
    #pragma unroll
    for (int off = 1; off < 32; off <<= 1) {
        int t = __shfl_up_sync(0xffffffffu, inc, off);
        if (lane >= off) inc += t;
    }
    __shared__ int ws[8];
    if (lane == 31) ws[wid] = inc;
    __syncthreads();
    __shared__ int wo[8];
    if (threadIdx.x == 0) {
        int run = 0;
        #pragma unroll
        for (int i = 0; i < 8; i++) { wo[i] = run; run += ws[i]; }
    }
    __syncthreads();
    int base = g_boff[b] + wo[wid] + (inc - tsum);   // exclusive prefix of this thread
    int p0 = base, p1 = base + d0, p2 = p1 + d1, p3 = p2 + d2;
    if (idx0 < n) {
        if (idx0 + 3 < n) {
            *(int4*)&g_ptr[idx0] = make_int4(p0, p1, p2, p3);
            *(int4*)&g_pos[idx0] = make_int4(p0, p1, p2, p3);
        } else {
            int pv[4] = {p0, p1, p2, p3};
            for (int i = 0; i < 4 && idx0 + i < n; i++) {
                g_ptr[idx0 + i] = pv[i];
                g_pos[idx0 + i] = pv[i];
            }
        }
        if (idx0 <= n - 1 && n - 1 < idx0 + 4) {     // owner of last element writes total
            int pv[4] = {p0, p1, p2, p3};
            int dv[4] = {d0, d1, d2, d3};
            int k = (n - 1) - idx0;
            g_ptr[n] = pv[k] + dv[k];
        }
    }
}

// ---------------- scatter src into dst-sorted order ----------------
__global__ void scatter_kernel(int E) {
    int e = blockIdx.x * blockDim.x + threadIdx.x;
    if (e >= E) return;
    int d = g_dst[e];
    int p = atomicAdd(&g_pos[d], 1);
    g_ssrc[p] = g_src[e];
}

// ---------------- generic fp32 SGEMM body: C[n,M] = A[n,K] @ B[K,M] ----------------
__device__ __forceinline__ void sgemm_body(const float* __restrict__ A,
                                           const float* __restrict__ B,
                                           float* __restrict__ C, int n, int K, int M) {
    __shared__ float As[64][17];
    __shared__ float Bs[16][64];
    int tid = threadIdx.x;
    int tx = tid & 15, ty = tid >> 4;
    int rowBase = blockIdx.y * 64;
    int colBase = blockIdx.x * 64;
    float acc[4][4] = {};
    for (int k0 = 0; k0 < K; k0 += 16) {
        {
            int r  = tid >> 2;
            int c4 = (tid & 3) * 4;
            float4 v = make_float4(0.f, 0.f, 0.f, 0.f);
            if (rowBase + r < n)
                v = *(const float4*)&A[(size_t)(rowBase + r) * K + k0 + c4];
            As[r][c4] = v.x; As[r][c4 + 1] = v.y; As[r][c4 + 2] = v.z; As[r][c4 + 3] = v.w;
        }
        {
            int r  = tid >> 4;
            int c4 = (tid & 15) * 4;
            *(float4*)&Bs[r][c4] = *(const float4*)&B[(size_t)(k0 + r) * M + colBase + c4];
        }
        __syncthreads();
        #pragma unroll
        for (int kk = 0; kk < 16; kk++) {
            float a[4], bb[4];
            #pragma unroll
            for (int i = 0; i < 4; i++) a[i] = As[ty * 4 + i][kk];
            #pragma unroll
            for (int j = 0; j < 4; j++) bb[j] = Bs[kk][tx * 4 + j];
            #pragma unroll
            for (int i = 0; i < 4; i++)
                #pragma unroll
                for (int j = 0; j < 4; j++)
                    acc[i][j] += a[i] * bb[j];
        }
        __syncthreads();
    }
    #pragma unroll
    for (int i = 0; i < 4; i++) {
        int r = rowBase + ty * 4 + i;
        if (r < n) {
            #pragma unroll
            for (int j = 0; j < 4; j++)
                C[(size_t)r * M + colBase + tx * 4 + j] = acc[i][j];
        }
    }
}

__global__ void sgemm1_kernel(const float* __restrict__ A, const float* __restrict__ B, int n) {
    sgemm_body(A, B, g_h1, n, 128, 128);
}
__global__ void sgemm2_kernel(const float* __restrict__ B, int n) {
    sgemm_body(g_hmid, B, g_h2, n, 128, 64);
}

// ---------------- layer1 node prep: attention logits only ----------------
__global__ void prep1_kernel(const float* __restrict__ att_s, const float* __restrict__ att_d, int n) {
    int w = (blockIdx.x * blockDim.x + threadIdx.x) >> 5;
    if (w >= n) return;
    int lane = threadIdx.x & 31;
    int c0 = lane * 4;
    float4 h  = *(const float4*)&g_h1[(size_t)w * 128 + c0];
    float4 s4 = *(const float4*)&att_s[c0];
    float4 d4 = *(const float4*)&att_d[c0];
    float ps = h.x * s4.x + h.y * s4.y + h.z * s4.z + h.w * s4.w;
    float pd = h.x * d4.x + h.y * d4.y + h.z * d4.z + h.w * d4.w;
    #pragma unroll
    for (int off = 8; off >= 1; off >>= 1) {   // reduce each 16-lane half
        ps += __shfl_down_sync(0xffffffffu, ps, off);
        pd += __shfl_down_sync(0xffffffffu, pd, off);
    }
    if (lane == 0)  { g_a1s[2 * w]     = ps; g_a1d[2 * w]     = pd; }
    if (lane == 16) { g_a1s[2 * w + 1] = ps; g_a1d[2 * w + 1] = pd; }
}

// ---------------- layer1 gather: softmax-weighted aggregation + bias + elu ----------------
// warp per node; no atomics
__global__ void gather1_kernel(const float* __restrict__ b1, int n) {
    int w = (blockIdx.x * blockDim.x + threadIdx.x) >> 5;
    if (w >= n) return;
    int lane = threadIdx.x & 31;
    int c0 = lane * 4;
    float a1d0 = g_a1d[2 * w], a1d1 = g_a1d[2 * w + 1];
    // self loop
    float ws0 = __expf(lrelu(g_a1s[2 * w]     + a1d0));
    float ws1 = __expf(lrelu(g_a1s[2 * w + 1] + a1d1));
    float4 hs = *(const float4*)&g_h1[(size_t)w * 128 + c0];
    float wws = (c0 < 64) ? ws0 : ws1;
    float4 acc = make_float4(hs.x * wws, hs.y * wws, hs.z * wws, hs.w * wws);
    float den0 = (lane == 0) ? ws0 : 0.f;
    float den1 = (lane == 0) ? ws1 : 0.f;
    int start = g_ptr[w], end = g_ptr[w + 1];
    for (int base = start; base < end; base += 32) {
        int j = base + lane;
        int s = 0; float e0 = 0.f, e1 = 0.f;
        if (j < end) {
            s = g_ssrc[j];
            float2 as = *(const float2*)&g_a1s[2 * s];
            e0 = __expf(lrelu(as.x + a1d0));
            e1 = __expf(lrelu(as.y + a1d1));
        }
        den0 += e0; den1 += e1;
        int m = min(32, end - base);
        for (int k = 0; k < m; k++) {
            int   sk  = __shfl_sync(0xffffffffu, s, k);
            float w0k = __shfl_sync(0xffffffffu, e0, k);
            float w1k = __shfl_sync(0xffffffffu, e1, k);
            float4 h = *(const float4*)&g_h1[(size_t)sk * 128 + c0];
            float ww = (c0 < 64) ? w0k : w1k;
            acc.x += h.x * ww; acc.y += h.y * ww; acc.z += h.z * ww; acc.w += h.w * ww;
        }
    }
    #pragma unroll
    for (int off = 16; off >= 1; off >>= 1) {
        den0 += __shfl_xor_sync(0xffffffffu, den0, off);
        den1 += __shfl_xor_sync(0xffffffffu, den1, off);
    }
    float r = 1.0f / (((c0 < 64) ? den0 : den1) + EPSQ);
    float4 o;
    o.x = elu1(acc.x * r + b1[c0]);
    o.y = elu1(acc.y * r + b1[c0 + 1]);
    o.z = elu1(acc.z * r + b1[c0 + 2]);
    o.w = elu1(acc.w * r + b1[c0 + 3]);
    *(float4*)&g_hmid[(size_t)w * 128 + c0] = o;
}

// ---------------- layer2 node prep ----------------
__global__ void prep2_kernel(const float* __restrict__ att_s, const float* __restrict__ att_d, int n) {
    int w = (blockIdx.x * blockDim.x + threadIdx.x) >> 5;
    if (w >= n) return;
    int lane = threadIdx.x & 31;
    int c0 = lane * 2;
    float2 h  = *(const float2*)&g_h2[(size_t)w * 64 + c0];
    float ps = h.x * att_s[c0] + h.y * att_s[c0 + 1];
    float pd = h.x * att_d[c0] + h.y * att_d[c0 + 1];
    #pragma unroll
    for (int off = 16; off >= 1; off >>= 1) {
        ps += __shfl_down_sync(0xffffffffu, ps, off);
        pd += __shfl_down_sync(0xffffffffu, pd, off);
    }
    if (lane == 0) { g_a2s[w] = ps; g_a2d[w] = pd; }
}

// ---------------- layer2 gather + bias + elu ----------------
__global__ void gather2_kernel(const float* __restrict__ b2, int n) {
    int w = (blockIdx.x * blockDim.x + threadIdx.x) >> 5;
    if (w >= n) return;
    int lane = threadIdx.x & 31;
    int c0 = lane * 2;
    float a2d = g_a2d[w];
    float ws0 = __expf(lrelu(g_a2s[w] + a2d));
    float2 hs = *(const float2*)&g_h2[(size_t)w * 64 + c0];
    float2 acc = make_float2(hs.x * ws0, hs.y * ws0);
    float den = (lane == 0) ? ws0 : 0.f;
    int start = g_ptr[w], end = g_ptr[w + 1];
    for (int base = start; base < end; base += 32) {
        int j = base + lane;
        int s = 0; float e0 = 0.f;
        if (j < end) {
            s = g_ssrc[j];
            e0 = __expf(lrelu(g_a2s[s] + a2d));
        }
        den += e0;
        int m = min(32, end - base);
        for (int k = 0; k < m; k++) {
            int   sk  = __shfl_sync(0xffffffffu, s, k);
            float w0k = __shfl_sync(0xffffffffu, e0, k);
            float2 h = *(const float2*)&g_h2[(size_t)sk * 64 + c0];
            acc.x += h.x * w0k; acc.y += h.y * w0k;
        }
    }
    #pragma unroll
    for (int off = 16; off >= 1; off >>= 1)
        den += __shfl_xor_sync(0xffffffffu, den, off);
    float r = 1.0f / (den + EPSQ);
    float2 o;
    o.x = elu1(acc.x * r + b2[c0]);
    o.y = elu1(acc.y * r + b2[c0 + 1]);
    *(float2*)&g_hout[(size_t)w * 64 + c0] = o;
}

// ---------------- final: @ lin_w + lin_b, sigmoid ----------------
__global__ void final_kernel(const float* __restrict__ lin_w, const float* __restrict__ lin_b,
                             float* __restrict__ out, int n) {
    __shared__ float sw[64 * 16];
    __shared__ float st[16][66];
    int tid = threadIdx.x;
    int nb = blockIdx.x * 16;
    #pragma unroll
    for (int i = 0; i < 4; i++) sw[tid + 256 * i] = lin_w[tid + 256 * i];
    #pragma unroll
    for (int i = 0; i < 4; i++) {
        int id = tid + 256 * i;          // 0..1023
        int g = id >> 6;
        int c = id & 63;
        int node = nb + g;
        st[g][c] = (node < n) ? g_hout[(size_t)node * 64 + c] : 0.f;
    }
    __syncthreads();
    int g = tid >> 4;
    int o = tid & 15;
    int node = nb + g;
    if (node >= n) return;
    float acc = lin_b[o];
    #pragma unroll
    for (int c = 0; c < 64; c++)
        acc += st[g][c] * sw[c * 16 + o];
    out[(size_t)node * 16 + o] = 1.0f / (1.0f + __expf(-acc));
}

// ---------------- launcher ----------------
extern "C" void kernel_launch(void* const* d_in, const int* in_sizes, int n_in,
                              void* d_out, int out_size) {
    const float* x        = (const float*)d_in[0];
    const void*  ei       = d_in[1];
    const float* W1       = (const float*)d_in[2];
    const float* att_src1 = (const float*)d_in[3];
    const float* att_dst1 = (const float*)d_in[4];
    const float* b1       = (const float*)d_in[5];
    const float* W2       = (const float*)d_in[6];
    const float* att_src2 = (const float*)d_in[7];
    const float* att_dst2 = (const float*)d_in[8];
    const float* b2       = (const float*)d_in[9];
    const float* lin_w    = (const float*)d_in[10];
    const float* lin_b    = (const float*)d_in[11];
    float*       out      = (float*)d_out;

    int n = in_sizes[0] / 128;        // 50000
    int E = in_sizes[1] / 2;          // 800000
    int nblk = (n + 1023) / 1024;     // 49 scan tiles

    // CSR build (shared by both layers)
    detect_kernel <<<1, 256>>>(ei, E, n);
    zero_kernel   <<<(n + 4 + 255) / 256, 256>>>(n);
    convert_kernel<<<(E + 255) / 256, 256>>>(ei, E);
    scanA_kernel  <<<nblk, 256>>>(n);
    scanB_kernel  <<<1, 64>>>(nblk);
    scanC_kernel  <<<nblk, 256>>>(n);
    scatter_kernel<<<(E + 255) / 256, 256>>>(E);

    // layer 1
    sgemm1_kernel <<<dim3(2, (n + 63) / 64), 256>>>(x, W1, n);
    prep1_kernel  <<<(n + 7) / 8, 256>>>(att_src1, att_dst1, n);
    gather1_kernel<<<(n + 7) / 8, 256>>>(b1, n);
    // layer 2
    sgemm2_kernel <<<dim3(1, (n + 63) / 64), 256>>>(W2, n);
    prep2_kernel  <<<(n + 7) / 8, 256>>>(att_src2, att_dst2, n);
    gather2_kernel<<<(n + 7) / 8, 256>>>(b2, n);
    // head
    final_kernel  <<<(n + 15) / 16, 256>>>(lin_w, lin_b, out, n);
}

// round 7
// speedup vs baseline: 2.2689x; 1.1058x over previous
#include <cuda_runtime.h>
#include <cuda_bf16.h>
#include <cstdint>

#define NN 50000
#define EE 800000
#define EPSQ 1e-16f

// ---------------- scratch (static device globals; no allocation) ----------------
__device__ float g_h1  [NN * 128];   // layer1 linear output [N,2,64]
__device__ float g_a1s [NN * 2];
__device__ float g_a1d [NN * 2];
__device__ float g_hmid[NN * 128];   // layer1 final (normalized+bias+elu) -> layer2 input
__device__ float g_h2  [NN * 64];
__device__ float g_a2s [NN];
__device__ float g_a2d [NN];
__device__ float g_hout[NN * 64];    // layer2 final (normalized+bias+elu)
__device__ int   g_src [EE];
__device__ int   g_dst [EE];
__device__ int   g_deg [NN + 4];     // +pad so int4 tail loads stay in-bounds
__device__ int   g_ptr [NN + 8];
__device__ int   g_pos [NN + 8];
__device__ int   g_ssrc[EE];         // src ids sorted by dst (CSR payload)
__device__ int   g_bsum[64];
__device__ int   g_boff[64];
__device__ int   g_e64;              // 1 if edge_index is int64, 0 if int32

__device__ __forceinline__ float lrelu(float x) { return x > 0.f ? x : 0.2f * x; }
__device__ __forceinline__ float elu1(float x)  { return x > 0.f ? x : expm1f(x); }

// ---------------- edge dtype detect ----------------
__global__ void detect_kernel(const void* ei, int E, int n) {
    __shared__ int ok;
    if (threadIdx.x == 0) ok = 1;
    __syncthreads();
    int stride = E > 256 ? E / 256 : 1;
    long long idx = (long long)threadIdx.x * stride;
    if (idx < E) {
        long long v = ((const long long*)ei)[idx];
        if (v < 0 || v >= n) ok = 0;   // benign race: all writers store 0
    }
    __syncthreads();
    if (threadIdx.x == 0) g_e64 = ok;
}

__global__ void zero_kernel(int n) {
    int i = blockIdx.x * blockDim.x + threadIdx.x;
    if (i < n + 4) g_deg[i] = 0;
}

// ---------------- convert + degree histogram ----------------
__global__ void convert_kernel(const void* ei, int E) {
    int e = blockIdx.x * blockDim.x + threadIdx.x;
    if (e >= E) return;
    int s, d;
    if (g_e64) {
        const long long* p = (const long long*)ei;
        s = (int)p[e];
        d = (int)p[E + e];
    } else {
        const int* p = (const int*)ei;
        s = p[e];
        d = p[E + e];
    }
    g_src[e] = s;
    g_dst[e] = d;
    atomicAdd(&g_deg[d], 1);
}

// ---------------- 3-phase parallel exclusive scan: g_deg -> g_ptr / g_pos ----------------
__global__ void scanA_kernel(int n) {
    int b = blockIdx.x;
    int base = b * 1024 + threadIdx.x * 4;
    int s = 0;
    if (base < n) {
        int4 v = *(const int4*)&g_deg[base];
        s = v.x + ((base + 1 < n) ? v.y : 0) + ((base + 2 < n) ? v.z : 0) + ((base + 3 < n) ? v.w : 0);
    }
    int lane = threadIdx.x & 31, wid = threadIdx.x >> 5;
    #pragma unroll
    for (int off = 16; off >= 1; off >>= 1) s += __shfl_xor_sync(0xffffffffu, s, off);
    __shared__ int ws[8];
    if (lane == 0) ws[wid] = s;
    __syncthreads();
    if (threadIdx.x == 0) {
        int t = 0;
        #pragma unroll
        for (int i = 0; i < 8; i++) t += ws[i];
        g_bsum[b] = t;
    }
}

__global__ void scanB_kernel(int nb) {
    int tid = threadIdx.x;
    int lane = tid & 31, w = tid >> 5;
    int v = (tid < nb) ? g_bsum[tid] : 0;
    int inc = v;
    #pragma unroll
    for (int off = 1; off < 32; off <<= 1) {
        int t = __shfl_up_sync(0xffffffffu, inc, off);
        if (lane >= off) inc += t;
    }
    __shared__ int wt[2];
    if (lane == 31) wt[w] = inc;
    __syncthreads();
    if (w == 1) inc += wt[0];
    g_boff[tid] = inc - v;   // exclusive
}

__global__ void scanC_kernel(int n) {
    int b = blockIdx.x;
    int idx0 = b * 1024 + threadIdx.x * 4;
    int d0 = 0, d1 = 0, d2 = 0, d3 = 0;
    if (idx0 < n) {
        int4 v = *(const int4*)&g_deg[idx0];
        d0 = v.x;
        d1 = (idx0 + 1 < n) ? v.y : 0;
        d2 = (idx0 + 2 < n) ? v.z : 0;
        d3 = (idx0 + 3 < n) ? v.w : 0;
    }
    int tsum = d0 + d1 + d2 + d3;
    int lane = threadIdx.x & 31, wid = threadIdx.x >> 5;
    int inc = tsum;
    #pragma unroll
    for (int off = 1; off < 32; off <<= 1) {
        int t = __shfl_up_sync(0xffffffffu, inc, off);
        if (lane >= off) inc += t;
    }
    __shared__ int ws[8];
    if (lane == 31) ws[wid] = inc;
    __syncthreads();
    __shared__ int wo[8];
    if (threadIdx.x == 0) {
        int run = 0;
        #pragma unroll
        for (int i = 0; i < 8; i++) { wo[i] = run; run += ws[i]; }
    }
    __syncthreads();
    int base = g_boff[b] + wo[wid] + (inc - tsum);
    int p0 = base, p1 = base + d0, p2 = p1 + d1, p3 = p2 + d2;
    if (idx0 < n) {
        if (idx0 + 3 < n) {
            *(int4*)&g_ptr[idx0] = make_int4(p0, p1, p2, p3);
            *(int4*)&g_pos[idx0] = make_int4(p0, p1, p2, p3);
        } else {
            int pv[4] = {p0, p1, p2, p3};
            for (int i = 0; i < 4 && idx0 + i < n; i++) {
                g_ptr[idx0 + i] = pv[i];
                g_pos[idx0 + i] = pv[i];
            }
        }
        if (idx0 <= n - 1 && n - 1 < idx0 + 4) {
            int pv[4] = {p0, p1, p2, p3};
            int dv[4] = {d0, d1, d2, d3};
            int k = (n - 1) - idx0;
            g_ptr[n] = pv[k] + dv[k];
        }
    }
}

// ---------------- scatter src into dst-sorted order ----------------
__global__ void scatter_kernel(int E) {
    int e = blockIdx.x * blockDim.x + threadIdx.x;
    if (e >= E) return;
    int d = g_dst[e];
    int p = atomicAdd(&g_pos[d], 1);
    g_ssrc[p] = g_src[e];
}

// ---------------- 3xTF32 tensor-core GEMM: C[n,M] = A[n,K] @ B[K,M] ----------------
// BM=128, BN=64, BK=32; 256 threads = 8 warps (4m x 2n), warp tile 32x32.
// Error ~2^-22 (near-fp32) via a = a_hi + a_lo split, skipping only lo*lo.
__device__ __forceinline__ void split_tf32(float x, uint32_t& hi, uint32_t& lo) {
    uint32_t h;
    asm("cvt.rna.tf32.f32 %0, %1;" : "=r"(h) : "f"(x));
    hi = h;
    lo = __float_as_uint(x - __uint_as_float(h));
}

__device__ __forceinline__ void mma8(float* c, const uint32_t* a, const uint32_t* b) {
    asm volatile(
        "mma.sync.aligned.m16n8k8.row.col.f32.tf32.tf32.f32 "
        "{%0,%1,%2,%3}, {%4,%5,%6,%7}, {%8,%9}, {%0,%1,%2,%3};"
        : "+f"(c[0]), "+f"(c[1]), "+f"(c[2]), "+f"(c[3])
        : "r"(a[0]), "r"(a[1]), "r"(a[2]), "r"(a[3]), "r"(b[0]), "r"(b[1]));
}

__device__ __forceinline__ void tf32_gemm_body(const float* __restrict__ A,
                                               const float* __restrict__ B,
                                               float* __restrict__ C,
                                               int n, int K, int M) {
    __shared__ float As[128][36];   // padded: conflict-free frag reads, 16B-aligned rows
    __shared__ float Bs[32][68];
    int tid  = threadIdx.x;
    int warp = tid >> 5, lane = tid & 31;
    int qr = lane >> 2, qc = lane & 3;
    int warpM = (warp >> 1) * 32;
    int warpN = (warp & 1) * 32;
    int rowBase = blockIdx.y * 128;
    int colBase = blockIdx.x * 64;

    float acc[2][4][4];
    #pragma unroll
    for (int mt = 0; mt < 2; mt++)
        #pragma unroll
        for (int nt = 0; nt < 4; nt++)
            #pragma unroll
            for (int i = 0; i < 4; i++) acc[mt][nt][i] = 0.f;

    for (int k0 = 0; k0 < K; k0 += 32) {
        // A tile: 128x32 = 1024 float4, 4 per thread
        #pragma unroll
        for (int i = 0; i < 4; i++) {
            int f = tid + 256 * i;
            int r = f >> 3, c4 = (f & 7) * 4;
            float4 v = make_float4(0.f, 0.f, 0.f, 0.f);
            if (rowBase + r < n)
                v = *(const float4*)&A[(size_t)(rowBase + r) * K + k0 + c4];
            *(float4*)&As[r][c4] = v;
        }
        // B tile: 32x64 = 512 float4, 2 per thread
        #pragma unroll
        for (int i = 0; i < 2; i++) {
            int f = tid + 256 * i;
            int r = f >> 4, c4 = (f & 15) * 4;
            *(float4*)&Bs[r][c4] = *(const float4*)&B[(size_t)(k0 + r) * M + colBase + c4];
        }
        __syncthreads();
        #pragma unroll
        for (int kk = 0; kk < 4; kk++) {
            int kb = kk * 8 + qc;
            uint32_t ah[2][4], al[2][4], bh[4][2], bl[4][2];
            #pragma unroll
            for (int mt = 0; mt < 2; mt++) {
                int r0 = warpM + mt * 16 + qr;
                split_tf32(As[r0][kb],         ah[mt][0], al[mt][0]);
                split_tf32(As[r0 + 8][kb],     ah[mt][1], al[mt][1]);
                split_tf32(As[r0][kb + 4],     ah[mt][2], al[mt][2]);
                split_tf32(As[r0 + 8][kb + 4], ah[mt][3], al[mt][3]);
            }
            #pragma unroll
            for (int nt = 0; nt < 4; nt++) {
                int nn = warpN + nt * 8 + qr;
                split_tf32(Bs[kb][nn],     bh[nt][0], bl[nt][0]);
                split_tf32(Bs[kb + 4][nn], bh[nt][1], bl[nt][1]);
            }
            #pragma unroll
            for (int mt = 0; mt < 2; mt++)
                #pragma unroll
                for (int nt = 0; nt < 4; nt++) {
                    mma8(acc[mt][nt], ah[mt], bl[nt]);   // hi*lo
                    mma8(acc[mt][nt], al[mt], bh[nt]);   // lo*hi
                    mma8(acc[mt][nt], ah[mt], bh[nt]);   // hi*hi
                }
        }
        __syncthreads();
    }
    // epilogue
    #pragma unroll
    for (int mt = 0; mt < 2; mt++) {
        int r0 = rowBase + warpM + mt * 16 + qr;
        #pragma unroll
        for (int nt = 0; nt < 4; nt++) {
            int cc = colBase + warpN + nt * 8 + qc * 2;
            if (r0 < n)
                *(float2*)&C[(size_t)r0 * M + cc] = make_float2(acc[mt][nt][0], acc[mt][nt][1]);
            if (r0 + 8 < n)
                *(float2*)&C[(size_t)(r0 + 8) * M + cc] = make_float2(acc[mt][nt][2], acc[mt][nt][3]);
        }
    }
}

__global__ void sgemm1_kernel(const float* __restrict__ A, const float* __restrict__ B, int n) {
    tf32_gemm_body(A, B, g_h1, n, 128, 128);
}
__global__ void sgemm2_kernel(const float* __restrict__ B, int n) {
    tf32_gemm_body(g_hmid, B, g_h2, n, 128, 64);
}

// ---------------- layer1 node prep: attention logits only ----------------
__global__ void prep1_kernel(const float* __restrict__ att_s, const float* __restrict__ att_d, int n) {
    int w = (blockIdx.x * blockDim.x + threadIdx.x) >> 5;
    if (w >= n) return;
    int lane = threadIdx.x & 31;
    int c0 = lane * 4;
    float4 h  = *(const float4*)&g_h1[(size_t)w * 128 + c0];
    float4 s4 = *(const float4*)&att_s[c0];
    float4 d4 = *(const float4*)&att_d[c0];
    float ps = h.x * s4.x + h.y * s4.y + h.z * s4.z + h.w * s4.w;
    float pd = h.x * d4.x + h.y * d4.y + h.z * d4.z + h.w * d4.w;
    #pragma unroll
    for (int off = 8; off >= 1; off >>= 1) {   // reduce each 16-lane half
        ps += __shfl_down_sync(0xffffffffu, ps, off);
        pd += __shfl_down_sync(0xffffffffu, pd, off);
    }
    if (lane == 0)  { g_a1s[2 * w]     = ps; g_a1d[2 * w]     = pd; }
    if (lane == 16) { g_a1s[2 * w + 1] = ps; g_a1d[2 * w + 1] = pd; }
}

// ---------------- layer1 gather: softmax-weighted aggregation + bias + elu ----------------
__global__ void gather1_kernel(const float* __restrict__ b1, int n) {
    int w = (blockIdx.x * blockDim.x + threadIdx.x) >> 5;
    if (w >= n) return;
    int lane = threadIdx.x & 31;
    int c0 = lane * 4;
    float a1d0 = g_a1d[2 * w], a1d1 = g_a1d[2 * w + 1];
    float ws0 = __expf(lrelu(g_a1s[2 * w]     + a1d0));
    float ws1 = __expf(lrelu(g_a1s[2 * w + 1] + a1d1));
    float4 hs = *(const float4*)&g_h1[(size_t)w * 128 + c0];
    float wws = (c0 < 64) ? ws0 : ws1;
    float4 acc = make_float4(hs.x * wws, hs.y * wws, hs.z * wws, hs.w * wws);
    float den0 = (lane == 0) ? ws0 : 0.f;
    float den1 = (lane == 0) ? ws1 : 0.f;
    int start = g_ptr[w], end = g_ptr[w + 1];
    for (int base = start; base < end; base += 32) {
        int j = base + lane;
        int s = 0; float e0 = 0.f, e1 = 0.f;
        if (j < end) {
            s = g_ssrc[j];
            float2 as = *(const float2*)&g_a1s[2 * s];
            e0 = __expf(lrelu(as.x + a1d0));
            e1 = __expf(lrelu(as.y + a1d1));
        }
        den0 += e0; den1 += e1;
        int m = min(32, end - base);
        for (int k = 0; k < m; k++) {
            int   sk  = __shfl_sync(0xffffffffu, s, k);
            float w0k = __shfl_sync(0xffffffffu, e0, k);
            float w1k = __shfl_sync(0xffffffffu, e1, k);
            float4 h = *(const float4*)&g_h1[(size_t)sk * 128 + c0];
            float ww = (c0 < 64) ? w0k : w1k;
            acc.x += h.x * ww; acc.y += h.y * ww; acc.z += h.z * ww; acc.w += h.w * ww;
        }
    }
    #pragma unroll
    for (int off = 16; off >= 1; off >>= 1) {
        den0 += __shfl_xor_sync(0xffffffffu, den0, off);
        den1 += __shfl_xor_sync(0xffffffffu, den1, off);
    }
    float r = 1.0f / (((c0 < 64) ? den0 : den1) + EPSQ);
    float4 o;
    o.x = elu1(acc.x * r + b1[c0]);
    o.y = elu1(acc.y * r + b1[c0 + 1]);
    o.z = elu1(acc.z * r + b1[c0 + 2]);
    o.w = elu1(acc.w * r + b1[c0 + 3]);
    *(float4*)&g_hmid[(size_t)w * 128 + c0] = o;
}

// ---------------- layer2 node prep ----------------
__global__ void prep2_kernel(const float* __restrict__ att_s, const float* __restrict__ att_d, int n) {
    int w = (blockIdx.x * blockDim.x + threadIdx.x) >> 5;
    if (w >= n) return;
    int lane = threadIdx.x & 31;
    int c0 = lane * 2;
    float2 h  = *(const float2*)&g_h2[(size_t)w * 64 + c0];
    float ps = h.x * att_s[c0] + h.y * att_s[c0 + 1];
    float pd = h.x * att_d[c0] + h.y * att_d[c0 + 1];
    #pragma unroll
    for (int off = 16; off >= 1; off >>= 1) {
        ps += __shfl_down_sync(0xffffffffu, ps, off);
        pd += __shfl_down_sync(0xffffffffu, pd, off);
    }
    if (lane == 0) { g_a2s[w] = ps; g_a2d[w] = pd; }
}

// ---------------- layer2 gather + bias + elu ----------------
__global__ void gather2_kernel(const float* __restrict__ b2, int n) {
    int w = (blockIdx.x * blockDim.x + threadIdx.x) >> 5;
    if (w >= n) return;
    int lane = threadIdx.x & 31;
    int c0 = lane * 2;
    float a2d = g_a2d[w];
    float ws0 = __expf(lrelu(g_a2s[w] + a2d));
    float2 hs = *(const float2*)&g_h2[(size_t)w * 64 + c0];
    float2 acc = make_float2(hs.x * ws0, hs.y * ws0);
    float den = (lane == 0) ? ws0 : 0.f;
    int start = g_ptr[w], end = g_ptr[w + 1];
    for (int base = start; base < end; base += 32) {
        int j = base + lane;
        int s = 0; float e0 = 0.f;
        if (j < end) {
            s = g_ssrc[j];
            e0 = __expf(lrelu(g_a2s[s] + a2d));
        }
        den += e0;
        int m = min(32, end - base);
        for (int k = 0; k < m; k++) {
            int   sk  = __shfl_sync(0xffffffffu, s, k);
            float w0k = __shfl_sync(0xffffffffu, e0, k);
            float2 h = *(const float2*)&g_h2[(size_t)sk * 64 + c0];
            acc.x += h.x * w0k; acc.y += h.y * w0k;
        }
    }
    #pragma unroll
    for (int off = 16; off >= 1; off >>= 1)
        den += __shfl_xor_sync(0xffffffffu, den, off);
    float r = 1.0f / (den + EPSQ);
    float2 o;
    o.x = elu1(acc.x * r + b2[c0]);
    o.y = elu1(acc.y * r + b2[c0 + 1]);
    *(float2*)&g_hout[(size_t)w * 64 + c0] = o;
}

// ---------------- final: @ lin_w + lin_b, sigmoid ----------------
__global__ void final_kernel(const float* __restrict__ lin_w, const float* __restrict__ lin_b,
                             float* __restrict__ out, int n) {
    __shared__ float sw[64 * 16];
    __shared__ float st[16][66];
    int tid = threadIdx.x;
    int nb = blockIdx.x * 16;
    #pragma unroll
    for (int i = 0; i < 4; i++) sw[tid + 256 * i] = lin_w[tid + 256 * i];
    #pragma unroll
    for (int i = 0; i < 4; i++) {
        int id = tid + 256 * i;          // 0..1023
        int g = id >> 6;
        int c = id & 63;
        int node = nb + g;
        st[g][c] = (node < n) ? g_hout[(size_t)node * 64 + c] : 0.f;
    }
    __syncthreads();
    int g = tid >> 4;
    int o = tid & 15;
    int node = nb + g;
    if (node >= n) return;
    float acc = lin_b[o];
    #pragma unroll
    for (int c = 0; c < 64; c++)
        acc += st[g][c] * sw[c * 16 + o];
    out[(size_t)node * 16 + o] = 1.0f / (1.0f + __expf(-acc));
}

// ---------------- launcher ----------------
extern "C" void kernel_launch(void* const* d_in, const int* in_sizes, int n_in,
                              void* d_out, int out_size) {
    const float* x        = (const float*)d_in[0];
    const void*  ei       = d_in[1];
    const float* W1       = (const float*)d_in[2];
    const float* att_src1 = (const float*)d_in[3];
    const float* att_dst1 = (const float*)d_in[4];
    const float* b1       = (const float*)d_in[5];
    const float* W2       = (const float*)d_in[6];
    const float* att_src2 = (const float*)d_in[7];
    const float* att_dst2 = (const float*)d_in[8];
    const float* b2       = (const float*)d_in[9];
    const float* lin_w    = (const float*)d_in[10];
    const float* lin_b    = (const float*)d_in[11];
    float*       out      = (float*)d_out;

    int n = in_sizes[0] / 128;        // 50000
    int E = in_sizes[1] / 2;          // 800000
    int nblk = (n + 1023) / 1024;     // 49 scan tiles
    int gy   = (n + 127) / 128;       // 391 gemm row tiles

    // CSR build (shared by both layers)
    detect_kernel <<<1, 256>>>(ei, E, n);
    zero_kernel   <<<(n + 4 + 255) / 256, 256>>>(n);
    convert_kernel<<<(E + 255) / 256, 256>>>(ei, E);
    scanA_kernel  <<<nblk, 256>>>(n);
    scanB_kernel  <<<1, 64>>>(nblk);
    scanC_kernel  <<<nblk, 256>>>(n);
    scatter_kernel<<<(E + 255) / 256, 256>>>(E);

    // layer 1
    sgemm1_kernel <<<dim3(2, gy), 256>>>(x, W1, n);
    prep1_kernel  <<<(n + 7) / 8, 256>>>(att_src1, att_dst1, n);
    gather1_kernel<<<(n + 7) / 8, 256>>>(b1, n);
    // layer 2
    sgemm2_kernel <<<dim3(1, gy), 256>>>(W2, n);
    prep2_kernel  <<<(n + 7) / 8, 256>>>(att_src2, att_dst2, n);
    gather2_kernel<<<(n + 7) / 8, 256>>>(b2, n);
    // head
    final_kernel  <<<(n + 15) / 16, 256>>>(lin_w, lin_b, out, n);
}

// round 9
// speedup vs baseline: 2.4842x; 1.0949x over previous
#include <cuda_runtime.h>
#include <cuda_bf16.h>
#include <cstdint>

#define NN 50000
#define EE 800000
#define EPSQ 1e-16f

// ---------------- scratch (static device globals; no allocation) ----------------
__device__ float g_h1  [NN * 128];   // layer1 linear output [N,2,64]
__device__ float g_a1s [NN * 2];
__device__ float g_a1d [NN * 2];
__device__ float g_hmid[NN * 128];   // layer1 final (normalized+bias+elu) -> layer2 input
__device__ float g_h2  [NN * 64];
__device__ float g_a2s [NN];
__device__ float g_a2d [NN];
__device__ float g_hout[NN * 64];    // layer2 final (normalized+bias+elu)
__device__ int   g_src [EE];
__device__ int   g_dst [EE];
__device__ int   g_deg [NN + 4];     // +pad so int4 tail loads stay in-bounds
__device__ int   g_ptr [NN + 8];
__device__ int   g_pos [NN + 8];
__device__ int   g_ssrc[EE];         // src ids sorted by dst (CSR payload)
__device__ int   g_bsum[64];
__device__ int   g_boff[64];
__device__ int   g_e64;              // 1 if edge_index is int64, 0 if int32

__device__ __forceinline__ float lrelu(float x) { return x > 0.f ? x : 0.2f * x; }
__device__ __forceinline__ float elu1(float x)  { return x > 0.f ? x : expm1f(x); }

// ---------------- edge dtype detect ----------------
__global__ void detect_kernel(const void* ei, int E, int n) {
    __shared__ int ok;
    if (threadIdx.x == 0) ok = 1;
    __syncthreads();
    int stride = E > 256 ? E / 256 : 1;
    long long idx = (long long)threadIdx.x * stride;
    if (idx < E) {
        long long v = ((const long long*)ei)[idx];
        if (v < 0 || v >= n) ok = 0;   // benign race: all writers store 0
    }
    __syncthreads();
    if (threadIdx.x == 0) g_e64 = ok;
}

__global__ void zero_kernel(int n) {
    int i = blockIdx.x * blockDim.x + threadIdx.x;
    if (i < n + 4) g_deg[i] = 0;
}

// ---------------- convert + degree histogram ----------------
__global__ void convert_kernel(const void* ei, int E) {
    int e = blockIdx.x * blockDim.x + threadIdx.x;
    if (e >= E) return;
    int s, d;
    if (g_e64) {
        const long long* p = (const long long*)ei;
        s = (int)p[e];
        d = (int)p[E + e];
    } else {
        const int* p = (const int*)ei;
        s = p[e];
        d = p[E + e];
    }
    g_src[e] = s;
    g_dst[e] = d;
    atomicAdd(&g_deg[d], 1);
}

// ---------------- 3-phase parallel exclusive scan: g_deg -> g_ptr / g_pos ----------------
__global__ void scanA_kernel(int n) {
    int b = blockIdx.x;
    int base = b * 1024 + threadIdx.x * 4;
    int s = 0;
    if (base < n) {
        int4 v = *(const int4*)&g_deg[base];
        s = v.x + ((base + 1 < n) ? v.y : 0) + ((base + 2 < n) ? v.z : 0) + ((base + 3 < n) ? v.w : 0);
    }
    int lane = threadIdx.x & 31, wid = threadIdx.x >> 5;
    #pragma unroll
    for (int off = 16; off >= 1; off >>= 1) s += __shfl_xor_sync(0xffffffffu, s, off);
    __shared__ int ws[8];
    if (lane == 0) ws[wid] = s;
    __syncthreads();
    if (threadIdx.x == 0) {
        int t = 0;
        #pragma unroll
        for (int i = 0; i < 8; i++) t += ws[i];
        g_bsum[b] = t;
    }
}

__global__ void scanB_kernel(int nb) {
    int tid = threadIdx.x;
    int lane = tid & 31, w = tid >> 5;
    int v = (tid < nb) ? g_bsum[tid] : 0;
    int inc = v;
    #pragma unroll
    for (int off = 1; off < 32; off <<= 1) {
        int t = __shfl_up_sync(0xffffffffu, inc, off);
        if (lane >= off) inc += t;
    }
    __shared__ int wt[2];
    if (lane == 31) wt[w] = inc;
    __syncthreads();
    if (w == 1) inc += wt[0];
    g_boff[tid] = inc - v;   // exclusive
}

__global__ void scanC_kernel(int n) {
    int b = blockIdx.x;
    int idx0 = b * 1024 + threadIdx.x * 4;
    int d0 = 0, d1 = 0, d2 = 0, d3 = 0;
    if (idx0 < n) {
        int4 v = *(const int4*)&g_deg[idx0];
        d0 = v.x;
        d1 = (idx0 + 1 < n) ? v.y : 0;
        d2 = (idx0 + 2 < n) ? v.z : 0;
        d3 = (idx0 + 3 < n) ? v.w : 0;
    }
    int tsum = d0 + d1 + d2 + d3;
    int lane = threadIdx.x & 31, wid = threadIdx.x >> 5;
    int inc = tsum;
    #pragma unroll
    for (int off = 1; off < 32; off <<= 1) {
        int t = __shfl_up_sync(0xffffffffu, inc, off);
        if (lane >= off) inc += t;
    }
    __shared__ int ws[8];
    if (lane == 31) ws[wid] = inc;
    __syncthreads();
    __shared__ int wo[8];
    if (threadIdx.x == 0) {
        int run = 0;
        #pragma unroll
        for (int i = 0; i < 8; i++) { wo[i] = run; run += ws[i]; }
    }
    __syncthreads();
    int base = g_boff[b] + wo[wid] + (inc - tsum);
    int p0 = base, p1 = base + d0, p2 = p1 + d1, p3 = p2 + d2;
    if (idx0 < n) {
        if (idx0 + 3 < n) {
            *(int4*)&g_ptr[idx0] = make_int4(p0, p1, p2, p3);
            *(int4*)&g_pos[idx0] = make_int4(p0, p1, p2, p3);
        } else {
            int pv[4] = {p0, p1, p2, p3};
            for (int i = 0; i < 4 && idx0 + i < n; i++) {
                g_ptr[idx0 + i] = pv[i];
                g_pos[idx0 + i] = pv[i];
            }
        }
        if (idx0 <= n - 1 && n - 1 < idx0 + 4) {
            int pv[4] = {p0, p1, p2, p3};
            int dv[4] = {d0, d1, d2, d3};
            int k = (n - 1) - idx0;
            g_ptr[n] = pv[k] + dv[k];
        }
    }
}

// ---------------- scatter src into dst-sorted order ----------------
__global__ void scatter_kernel(int E) {
    int e = blockIdx.x * blockDim.x + threadIdx.x;
    if (e >= E) return;
    int d = g_dst[e];
    int p = atomicAdd(&g_pos[d], 1);
    g_ssrc[p] = g_src[e];
}

// ---------------- 3xTF32 tensor-core GEMM + fused attention-logit epilogue ----------------
// C[n,M] = A[n,K] @ B[K,M];  out_s[row*lstride+head] = C_blockcols(row) . att_s[head],
// likewise out_d. Each 64-col block tile == one attention head, so the logit dot is
// computable from block accumulators alone. K must be a multiple of 32 (here 128).
// BM=128, BN=64, BK=32; 256 threads = 8 warps (4m x 2n), warp tile 32x32.
// Register-prefetch pipeline overlaps the k+1 tile LDGs with the k-tile MMA work.
__device__ __forceinline__ void split_tf32(float x, uint32_t& hi, uint32_t& lo) {
    uint32_t h;
    asm("cvt.rna.tf32.f32 %0, %1;" : "=r"(h) : "f"(x));
    hi = h;
    lo = __float_as_uint(x - __uint_as_float(h));
}

__device__ __forceinline__ void mma8(float* c, const uint32_t* a, const uint32_t* b) {
    asm volatile(
        "mma.sync.aligned.m16n8k8.row.col.f32.tf32.tf32.f32 "
        "{%0,%1,%2,%3}, {%4,%5,%6,%7}, {%8,%9}, {%0,%1,%2,%3};"
        : "+f"(c[0]), "+f"(c[1]), "+f"(c[2]), "+f"(c[3])
        : "r"(a[0]), "r"(a[1]), "r"(a[2]), "r"(a[3]), "r"(b[0]), "r"(b[1]));
}

__device__ __forceinline__ void tf32_gemm_body(const float* __restrict__ A,
                                               const float* __restrict__ B,
                                               float* __restrict__ C,
                                               int n, int K, int M,
                                               const float* __restrict__ att_s,
                                               const float* __restrict__ att_d,
                                               float* __restrict__ out_s,
                                               float* __restrict__ out_d,
                                               int lstride) {
    __shared__ float As[128][36];   // padded: conflict-free frag reads, 16B-aligned rows
    __shared__ float Bs[32][68];
    __shared__ float s_as[64], s_ad[64];
    int tid  = threadIdx.x;
    int warp = tid >> 5, lane = tid & 31;
    int qr = lane >> 2, qc = lane & 3;
    int warpM = (warp >> 1) * 32;
    int warpN = (warp & 1) * 32;
    int rowBase = blockIdx.y * 128;
    int colBase = blockIdx.x * 64;
    int head    = blockIdx.x;       // one head per 64-col tile

    if (tid < 64) {
        s_as[tid] = att_s[head * 64 + tid];
        s_ad[tid] = att_d[head * 64 + tid];
    }

    float acc[2][4][4];
    #pragma unroll
    for (int mt = 0; mt < 2; mt++)
        #pragma unroll
        for (int nt = 0; nt < 4; nt++)
            #pragma unroll
            for (int i = 0; i < 4; i++) acc[mt][nt][i] = 0.f;

    // ---- register prefetch state ----
    int ar = tid >> 3, ac4 = (tid & 7) * 4;      // A: thread loads rows ar, ar+... 4 frags
    int br = tid >> 4, bc4 = (tid & 15) * 4;     // B: 2 frags
    float4 pa[4], pb[2];

    // prefetch tile 0
    #pragma unroll
    for (int i = 0; i < 4; i++) {
        int r = (tid + 256 * i) >> 3;
        int c4 = ((tid + 256 * i) & 7) * 4;
        pa[i] = make_float4(0.f, 0.f, 0.f, 0.f);
        if (rowBase + r < n)
            pa[i] = *(const float4*)&A[(size_t)(rowBase + r) * K + c4];
        (void)ar; (void)ac4;
    }
    #pragma unroll
    for (int i = 0; i < 2; i++) {
        int r = (tid + 256 * i) >> 4;
        int c4 = ((tid + 256 * i) & 15) * 4;
        pb[i] = *(const float4*)&B[(size_t)r * M + colBase + c4];
        (void)br; (void)bc4;
    }

    int nsteps = K >> 5;                          // K/32 tiles (K=128 -> 4)
    for (int t = 0; t < nsteps; t++) {
        // commit prefetched tile to smem
        #pragma unroll
        for (int i = 0; i < 4; i++) {
            int f = tid + 256 * i;
            *(float4*)&As[f >> 3][(f & 7) * 4] = pa[i];
        }
        #pragma unroll
        for (int i = 0; i < 2; i++) {
            int f = tid + 256 * i;
            *(float4*)&Bs[f >> 4][(f & 15) * 4] = pb[i];
        }
        __syncthreads();
        // issue next tile's loads before compute (latency overlap)
        if (t + 1 < nsteps) {
            int k0 = (t + 1) * 32;
            #pragma unroll
            for (int i = 0; i < 4; i++) {
                int f = tid + 256 * i;
                int r = f >> 3, c4 = (f & 7) * 4;
                pa[i] = make_float4(0.f, 0.f, 0.f, 0.f);
                if (rowBase + r < n)
                    pa[i] = *(const float4*)&A[(size_t)(rowBase + r) * K + k0 + c4];
            }
            #pragma unroll
            for (int i = 0; i < 2; i++) {
                int f = tid + 256 * i;
                int r = f >> 4, c4 = (f & 15) * 4;
                pb[i] = *(const float4*)&B[(size_t)(k0 + r) * M + colBase + c4];
            }
        }
        #pragma unroll
        for (int kk = 0; kk < 4; kk++) {
            int kb = kk * 8 + qc;
            uint32_t ah[2][4], al[2][4], bh[4][2], bl[4][2];
            #pragma unroll
            for (int mt = 0; mt < 2; mt++) {
                int r0 = warpM + mt * 16 + qr;
                split_tf32(As[r0][kb],         ah[mt][0], al[mt][0]);
                split_tf32(As[r0 + 8][kb],     ah[mt][1], al[mt][1]);
                split_tf32(As[r0][kb + 4],     ah[mt][2], al[mt][2]);
                split_tf32(As[r0 + 8][kb + 4], ah[mt][3], al[mt][3]);
            }
            #pragma unroll
            for (int nt = 0; nt < 4; nt++) {
                int nn = warpN + nt * 8 + qr;
                split_tf32(Bs[kb][nn],     bh[nt][0], bl[nt][0]);
                split_tf32(Bs[kb + 4][nn], bh[nt][1], bl[nt][1]);
            }
            #pragma unroll
            for (int mt = 0; mt < 2; mt++)
                #pragma unroll
                for (int nt = 0; nt < 4; nt++) {
                    mma8(acc[mt][nt], ah[mt], bl[nt]);   // hi*lo
                    mma8(acc[mt][nt], al[mt], bh[nt]);   // lo*hi
                    mma8(acc[mt][nt], ah[mt], bh[nt]);   // hi*hi
                }
        }
        __syncthreads();
    }

    // ---- epilogue 1: store C ----
    #pragma unroll
    for (int mt = 0; mt < 2; mt++) {
        int r0 = rowBase + warpM + mt * 16 + qr;
        #pragma unroll
        for (int nt = 0; nt < 4; nt++) {
            int cc = colBase + warpN + nt * 8 + qc * 2;
            if (r0 < n)
                *(float2*)&C[(size_t)r0 * M + cc] = make_float2(acc[mt][nt][0], acc[mt][nt][1]);
            if (r0 + 8 < n)
                *(float2*)&C[(size_t)(r0 + 8) * M + cc] = make_float2(acc[mt][nt][2], acc[mt][nt][3]);
        }
    }

    // ---- epilogue 2: fused attention logits ----
    // per-thread partial dot over this thread's accumulator columns
    float psum[4] = {0.f, 0.f, 0.f, 0.f};   // rows warpM+qr+{0,8,16,24}
    float pdsum[4] = {0.f, 0.f, 0.f, 0.f};
    #pragma unroll
    for (int mt = 0; mt < 2; mt++)
        #pragma unroll
        for (int nt = 0; nt < 4; nt++) {
            int cl = warpN + nt * 8 + qc * 2;    // block-local column
            float as0 = s_as[cl], as1 = s_as[cl + 1];
            float ad0 = s_ad[cl], ad1 = s_ad[cl + 1];
            psum [mt * 2 + 0] += acc[mt][nt][0] * as0 + acc[mt][nt][1] * as1;
            pdsum[mt * 2 + 0] += acc[mt][nt][0] * ad0 + acc[mt][nt][1] * ad1;
            psum [mt * 2 + 1] += acc[mt][nt][2] * as0 + acc[mt][nt][3] * as1;
            pdsum[mt * 2 + 1] += acc[mt][nt][2] * ad0 + acc[mt][nt][3] * ad1;
        }
    // reduce over the 4 qc lanes (lane bits 0-1)
    #pragma unroll
    for (int off = 1; off <= 2; off <<= 1)
        #pragma unroll
        for (int j = 0; j < 4; j++) {
            psum[j]  += __shfl_xor_sync(0xffffffffu, psum[j],  off);
            pdsum[j] += __shfl_xor_sync(0xffffffffu, pdsum[j], off);
        }
    // cross n-warp combine through reused As smem
    float* red_s = &As[0][0];         // 128 floats
    float* red_d = &As[0][0] + 128;
    __syncthreads();                  // all warps done with As/Bs
    if ((warp & 1) == 0 && qc == 0) {
        #pragma unroll
        for (int j = 0; j < 4; j++) {
            int row = warpM + (j >> 1) * 16 + (j & 1) * 8 + qr;
            red_s[row] = psum[j];
            red_d[row] = pdsum[j];
        }
    }
    __syncthreads();
    if ((warp & 1) == 1 && qc == 0) {
        #pragma unroll
        for (int j = 0; j < 4; j++) {
            int row = warpM + (j >> 1) * 16 + (j & 1) * 8 + qr;
            int grow = rowBase + row;
            if (grow < n) {
                out_s[(size_t)grow * lstride + head] = red_s[row] + psum[j];
                out_d[(size_t)grow * lstride + head] = red_d[row] + pdsum[j];
            }
        }
    }
}

__global__ void sgemm1_kernel(const float* __restrict__ A, const float* __restrict__ B,
                              const float* __restrict__ att_s, const float* __restrict__ att_d,
                              int n) {
    tf32_gemm_body(A, B, g_h1, n, 128, 128, att_s, att_d, g_a1s, g_a1d, 2);
}
__global__ void sgemm2_kernel(const float* __restrict__ B,
                              const float* __restrict__ att_s, const float* __restrict__ att_d,
                              int n) {
    tf32_gemm_body(g_hmid, B, g_h2, n, 128, 64, att_s, att_d, g_a2s, g_a2d, 1);
}

// ---------------- layer1 gather: softmax-weighted aggregation + bias + elu ----------------
__global__ void gather1_kernel(const float* __restrict__ b1, int n) {
    int w = (blockIdx.x * blockDim.x + threadIdx.x) >> 5;
    if (w >= n) return;
    int lane = threadIdx.x & 31;
    int c0 = lane * 4;
    float a1d0 = g_a1d[2 * w], a1d1 = g_a1d[2 * w + 1];
    float ws0 = __expf(lrelu(g_a1s[2 * w]     + a1d0));
    float ws1 = __expf(lrelu(g_a1s[2 * w + 1] + a1d1));
    float4 hs = *(const float4*)&g_h1[(size_t)w * 128 + c0];
    float wws = (c0 < 64) ? ws0 : ws1;
    float4 acc = make_float4(hs.x * wws, hs.y * wws, hs.z * wws, hs.w * wws);
    float den0 = (lane == 0) ? ws0 : 0.f;
    float den1 = (lane == 0) ? ws1 : 0.f;
    int start = g_ptr[w], end = g_ptr[w + 1];
    for (int base = start; base < end; base += 32) {
        int j = base + lane;
        int s = 0; float e0 = 0.f, e1 = 0.f;
        if (j < end) {
            s = g_ssrc[j];
            float2 as = *(const float2*)&g_a1s[2 * s];
            e0 = __expf(lrelu(as.x + a1d0));
            e1 = __expf(lrelu(as.y + a1d1));
        }
        den0 += e0; den1 += e1;
        int m = min(32, end - base);
        for (int k = 0; k < m; k++) {
            int   sk  = __shfl_sync(0xffffffffu, s, k);
            float w0k = __shfl_sync(0xffffffffu, e0, k);
            float w1k = __shfl_sync(0xffffffffu, e1, k);
            float4 h = *(const float4*)&g_h1[(size_t)sk * 128 + c0];
            float ww = (c0 < 64) ? w0k : w1k;
            acc.x += h.x * ww; acc.y += h.y * ww; acc.z += h.z * ww; acc.w += h.w * ww;
        }
    }
    #pragma unroll
    for (int off = 16; off >= 1; off >>= 1) {
        den0 += __shfl_xor_sync(0xffffffffu, den0, off);
        den1 += __shfl_xor_sync(0xffffffffu, den1, off);
    }
    float r = 1.0f / (((c0 < 64) ? den0 : den1) + EPSQ);
    float4 o;
    o.x = elu1(acc.x * r + b1[c0]);
    o.y = elu1(acc.y * r + b1[c0 + 1]);
    o.z = elu1(acc.z * r + b1[c0 + 2]);
    o.w = elu1(acc.w * r + b1[c0 + 3]);
    *(float4*)&g_hmid[(size_t)w * 128 + c0] = o;
}

// ---------------- layer2 gather + bias + elu ----------------
__global__ void gather2_kernel(const float* __restrict__ b2, int n) {
    int w = (blockIdx.x * blockDim.x + threadIdx.x) >> 5;
    if (w >= n) return;
    int lane = threadIdx.x & 31;
    int c0 = lane * 2;
    float a2d = g_a2d[w];
    float ws0 = __expf(lrelu(g_a2s[w] + a2d));
    float2 hs = *(const float2*)&g_h2[(size_t)w * 64 + c0];
    float2 acc = make_float2(hs.x * ws0, hs.y * ws0);
    float den = (lane == 0) ? ws0 : 0.f;
    int start = g_ptr[w], end = g_ptr[w + 1];
    for (int base = start; base < end; base += 32) {
        int j = base + lane;
        int s = 0; float e0 = 0.f;
        if (j < end) {
            s = g_ssrc[j];
            e0 = __expf(lrelu(g_a2s[s] + a2d));
        }
        den += e0;
        int m = min(32, end - base);
        for (int k = 0; k < m; k++) {
            int   sk  = __shfl_sync(0xffffffffu, s, k);
            float w0k = __shfl_sync(0xffffffffu, e0, k);
            float2 h = *(const float2*)&g_h2[(size_t)sk * 64 + c0];
            acc.x += h.x * w0k; acc.y += h.y * w0k;
        }
    }
    #pragma unroll
    for (int off = 16; off >= 1; off >>= 1)
        den += __shfl_xor_sync(0xffffffffu, den, off);
    float r = 1.0f / (den + EPSQ);
    float2 o;
    o.x = elu1(acc.x * r + b2[c0]);
    o.y = elu1(acc.y * r + b2[c0 + 1]);
    *(float2*)&g_hout[(size_t)w * 64 + c0] = o;
}

// ---------------- final: @ lin_w + lin_b, sigmoid ----------------
__global__ void final_kernel(const float* __restrict__ lin_w, const float* __restrict__ lin_b,
                             float* __restrict__ out, int n) {
    __shared__ float sw[64 * 16];
    __shared__ float st[16][66];
    int tid = threadIdx.x;
    int nb = blockIdx.x * 16;
    #pragma unroll
    for (int i = 0; i < 4; i++) sw[tid + 256 * i] = lin_w[tid + 256 * i];
    #pragma unroll
    for (int i = 0; i < 4; i++) {
        int id = tid + 256 * i;          // 0..1023
        int g = id >> 6;
        int c = id & 63;
        int node = nb + g;
        st[g][c] = (node < n) ? g_hout[(size_t)node * 64 + c] : 0.f;
    }
    __syncthreads();
    int g = tid >> 4;
    int o = tid & 15;
    int node = nb + g;
    if (node >= n) return;
    float acc = lin_b[o];
    #pragma unroll
    for (int c = 0; c < 64; c++)
        acc += st[g][c] * sw[c * 16 + o];
    out[(size_t)node * 16 + o] = 1.0f / (1.0f + __expf(-acc));
}

// ---------------- launcher ----------------
extern "C" void kernel_launch(void* const* d_in, const int* in_sizes, int n_in,
                              void* d_out, int out_size) {
    const float* x        = (const float*)d_in[0];
    const void*  ei       = d_in[1];
    const float* W1       = (const float*)d_in[2];
    const float* att_src1 = (const float*)d_in[3];
    const float* att_dst1 = (const float*)d_in[4];
    const float* b1       = (const float*)d_in[5];
    const float* W2       = (const float*)d_in[6];
    const float* att_src2 = (const float*)d_in[7];
    const float* att_dst2 = (const float*)d_in[8];
    const float* b2       = (const float*)d_in[9];
    const float* lin_w    = (const float*)d_in[10];
    const float* lin_b    = (const float*)d_in[11];
    float*       out      = (float*)d_out;

    int n = in_sizes[0] / 128;        // 50000
    int E = in_sizes[1] / 2;          // 800000
    int nblk = (n + 1023) / 1024;     // 49 scan tiles
    int gy   = (n + 127) / 128;       // 391 gemm row tiles

    // CSR build (shared by both layers)
    detect_kernel <<<1, 256>>>(ei, E, n);
    zero_kernel   <<<(n + 4 + 255) / 256, 256>>>(n);
    convert_kernel<<<(E + 255) / 256, 256>>>(ei, E);
    scanA_kernel  <<<nblk, 256>>>(n);
    scanB_kernel  <<<1, 64>>>(nblk);
    scanC_kernel  <<<nblk, 256>>>(n);
    scatter_kernel<<<(E + 255) / 256, 256>>>(E);

    // layer 1 (logits fused into GEMM epilogue)
    sgemm1_kernel <<<dim3(2, gy), 256>>>(x, W1, att_src1, att_dst1, n);
    gather1_kernel<<<(n + 7) / 8, 256>>>(b1, n);
    // layer 2
    sgemm2_kernel <<<dim3(1, gy), 256>>>(W2, att_src2, att_dst2, n);
    gather2_kernel<<<(n + 7) / 8, 256>>>(b2, n);
    // head
    final_kernel  <<<(n + 15) / 16, 256>>>(lin_w, lin_b, out, n);
}

// round 10
// speedup vs baseline: 2.5036x; 1.0078x over previous
#include <cuda_runtime.h>
#include <cuda_bf16.h>
#include <cuda_fp16.h>
#include <cstdint>

#define NN 50000
#define EE 800000
#define EPSQ 1e-16f

// ---------------- scratch (static device globals; no allocation) ----------------
__device__ float   g_h1  [NN * 128];   // layer1 linear output [N,2,64] (fp32, for logits/selfloop path consistency)
__device__ __half2 g_h1h [NN * 64];    // fp16 copy for gather traffic (256B/row)
__device__ float   g_a1s [NN * 2];
__device__ float   g_a1d [NN * 2];
__device__ float   g_hmid[NN * 128];   // layer1 final (normalized+bias+elu) -> layer2 input
__device__ float   g_h2  [NN * 64];
__device__ __half2 g_h2h [NN * 32];    // fp16 copy (128B/row)
__device__ float   g_a2s [NN];
__device__ float   g_a2d [NN];
__device__ float   g_hout[NN * 64];    // layer2 final (normalized+bias+elu)
__device__ int     g_src [EE];
__device__ int     g_dst [EE];
__device__ int     g_deg [NN + 4];     // +pad so int4 tail loads stay in-bounds
__device__ int     g_ptr [NN + 8];
__device__ int     g_pos [NN + 8];
__device__ int     g_ssrc[EE];         // src ids sorted by dst (CSR payload)
__device__ int     g_bsum[64];
__device__ int     g_boff[64];
__device__ int     g_e64;              // 1 if edge_index is int64, 0 if int32

__device__ __forceinline__ float lrelu(float x) { return x > 0.f ? x : 0.2f * x; }
__device__ __forceinline__ float elu1(float x)  { return x > 0.f ? x : expm1f(x); }

// ---------------- edge dtype detect ----------------
__global__ void detect_kernel(const void* ei, int E, int n) {
    __shared__ int ok;
    if (threadIdx.x == 0) ok = 1;
    __syncthreads();
    int stride = E > 256 ? E / 256 : 1;
    long long idx = (long long)threadIdx.x * stride;
    if (idx < E) {
        long long v = ((const long long*)ei)[idx];
        if (v < 0 || v >= n) ok = 0;   // benign race: all writers store 0
    }
    __syncthreads();
    if (threadIdx.x == 0) g_e64 = ok;
}

__global__ void zero_kernel(int n) {
    int i = blockIdx.x * blockDim.x + threadIdx.x;
    if (i < n + 4) g_deg[i] = 0;
}

// ---------------- convert + degree histogram ----------------
__global__ void convert_kernel(const void* ei, int E) {
    int e = blockIdx.x * blockDim.x + threadIdx.x;
    if (e >= E) return;
    int s, d;
    if (g_e64) {
        const long long* p = (const long long*)ei;
        s = (int)p[e];
        d = (int)p[E + e];
    } else {
        const int* p = (const int*)ei;
        s = p[e];
        d = p[E + e];
    }
    g_src[e] = s;
    g_dst[e] = d;
    atomicAdd(&g_deg[d], 1);
}

// ---------------- 3-phase parallel exclusive scan: g_deg -> g_ptr / g_pos ----------------
__global__ void scanA_kernel(int n) {
    int b = blockIdx.x;
    int base = b * 1024 + threadIdx.x * 4;
    int s = 0;
    if (base < n) {
        int4 v = *(const int4*)&g_deg[base];
        s = v.x + ((base + 1 < n) ? v.y : 0) + ((base + 2 < n) ? v.z : 0) + ((base + 3 < n) ? v.w : 0);
    }
    int lane = threadIdx.x & 31, wid = threadIdx.x >> 5;
    #pragma unroll
    for (int off = 16; off >= 1; off >>= 1) s += __shfl_xor_sync(0xffffffffu, s, off);
    __shared__ int ws[8];
    if (lane == 0) ws[wid] = s;
    __syncthreads();
    if (threadIdx.x == 0) {
        int t = 0;
        #pragma unroll
        for (int i = 0; i < 8; i++) t += ws[i];
        g_bsum[b] = t;
    }
}

__global__ void scanB_kernel(int nb) {
    int tid = threadIdx.x;
    int lane = tid & 31, w = tid >> 5;
    int v = (tid < nb) ? g_bsum[tid] : 0;
    int inc = v;
    #pragma unroll
    for (int off = 1; off < 32; off <<= 1) {
        int t = __shfl_up_sync(0xffffffffu, inc, off);
        if (lane >= off) inc += t;
    }
    __shared__ int wt[2];
    if (lane == 31) wt[w] = inc;
    __syncthreads();
    if (w == 1) inc += wt[0];
    g_boff[tid] = inc - v;   // exclusive
}

__global__ void scanC_kernel(int n) {
    int b = blockIdx.x;
    int idx0 = b * 1024 + threadIdx.x * 4;
    int d0 = 0, d1 = 0, d2 = 0, d3 = 0;
    if (idx0 < n) {
        int4 v = *(const int4*)&g_deg[idx0];
        d0 = v.x;
        d1 = (idx0 + 1 < n) ? v.y : 0;
        d2 = (idx0 + 2 < n) ? v.z : 0;
        d3 = (idx0 + 3 < n) ? v.w : 0;
    }
    int tsum = d0 + d1 + d2 + d3;
    int lane = threadIdx.x & 31, wid = threadIdx.x >> 5;
    int inc = tsum;
    #pragma unroll
    for (int off = 1; off < 32; off <<= 1) {
        int t = __shfl_up_sync(0xffffffffu, inc, off);
        if (lane >= off) inc += t;
    }
    __shared__ int ws[8];
    if (lane == 31) ws[wid] = inc;
    __syncthreads();
    __shared__ int wo[8];
    if (threadIdx.x == 0) {
        int run = 0;
        #pragma unroll
        for (int i = 0; i < 8; i++) { wo[i] = run; run += ws[i]; }
    }
    __syncthreads();
    int base = g_boff[b] + wo[wid] + (inc - tsum);
    int p0 = base, p1 = base + d0, p2 = p1 + d1, p3 = p2 + d2;
    if (idx0 < n) {
        if (idx0 + 3 < n) {
            *(int4*)&g_ptr[idx0] = make_int4(p0, p1, p2, p3);
            *(int4*)&g_pos[idx0] = make_int4(p0, p1, p2, p3);
        } else {
            int pv[4] = {p0, p1, p2, p3};
            for (int i = 0; i < 4 && idx0 + i < n; i++) {
                g_ptr[idx0 + i] = pv[i];
                g_pos[idx0 + i] = pv[i];
            }
        }
        if (idx0 <= n - 1 && n - 1 < idx0 + 4) {
            int pv[4] = {p0, p1, p2, p3};
            int dv[4] = {d0, d1, d2, d3};
            int k = (n - 1) - idx0;
            g_ptr[n] = pv[k] + dv[k];
        }
    }
}

// ---------------- scatter src into dst-sorted order ----------------
__global__ void scatter_kernel(int E) {
    int e = blockIdx.x * blockDim.x + threadIdx.x;
    if (e >= E) return;
    int d = g_dst[e];
    int p = atomicAdd(&g_pos[d], 1);
    g_ssrc[p] = g_src[e];
}

// ---------------- 3xTF32 tensor-core GEMM + fused logits + fp16 side copy ----------------
__device__ __forceinline__ void split_tf32(float x, uint32_t& hi, uint32_t& lo) {
    uint32_t h;
    asm("cvt.rna.tf32.f32 %0, %1;" : "=r"(h) : "f"(x));
    hi = h;
    lo = __float_as_uint(x - __uint_as_float(h));
}

__device__ __forceinline__ void mma8(float* c, const uint32_t* a, const uint32_t* b) {
    asm volatile(
        "mma.sync.aligned.m16n8k8.row.col.f32.tf32.tf32.f32 "
        "{%0,%1,%2,%3}, {%4,%5,%6,%7}, {%8,%9}, {%0,%1,%2,%3};"
        : "+f"(c[0]), "+f"(c[1]), "+f"(c[2]), "+f"(c[3])
        : "r"(a[0]), "r"(a[1]), "r"(a[2]), "r"(a[3]), "r"(b[0]), "r"(b[1]));
}

__device__ __forceinline__ void tf32_gemm_body(const float* __restrict__ A,
                                               const float* __restrict__ B,
                                               float* __restrict__ C,
                                               __half2* __restrict__ Ch,   // fp16 copy, M/2 per row
                                               int n, int K, int M,
                                               const float* __restrict__ att_s,
                                               const float* __restrict__ att_d,
                                               float* __restrict__ out_s,
                                               float* __restrict__ out_d,
                                               int lstride) {
    __shared__ float As[128][36];
    __shared__ float Bs[32][68];
    __shared__ float s_as[64], s_ad[64];
    int tid  = threadIdx.x;
    int warp = tid >> 5, lane = tid & 31;
    int qr = lane >> 2, qc = lane & 3;
    int warpM = (warp >> 1) * 32;
    int warpN = (warp & 1) * 32;
    int rowBase = blockIdx.y * 128;
    int colBase = blockIdx.x * 64;
    int head    = blockIdx.x;       // one head per 64-col tile
    int Mh      = M >> 1;

    if (tid < 64) {
        s_as[tid] = att_s[head * 64 + tid];
        s_ad[tid] = att_d[head * 64 + tid];
    }

    float acc[2][4][4];
    #pragma unroll
    for (int mt = 0; mt < 2; mt++)
        #pragma unroll
        for (int nt = 0; nt < 4; nt++)
            #pragma unroll
            for (int i = 0; i < 4; i++) acc[mt][nt][i] = 0.f;

    float4 pa[4], pb[2];
    // prefetch tile 0
    #pragma unroll
    for (int i = 0; i < 4; i++) {
        int f = tid + 256 * i;
        int r = f >> 3, c4 = (f & 7) * 4;
        pa[i] = make_float4(0.f, 0.f, 0.f, 0.f);
        if (rowBase + r < n)
            pa[i] = *(const float4*)&A[(size_t)(rowBase + r) * K + c4];
    }
    #pragma unroll
    for (int i = 0; i < 2; i++) {
        int f = tid + 256 * i;
        int r = f >> 4, c4 = (f & 15) * 4;
        pb[i] = *(const float4*)&B[(size_t)r * M + colBase + c4];
    }

    int nsteps = K >> 5;
    for (int t = 0; t < nsteps; t++) {
        #pragma unroll
        for (int i = 0; i < 4; i++) {
            int f = tid + 256 * i;
            *(float4*)&As[f >> 3][(f & 7) * 4] = pa[i];
        }
        #pragma unroll
        for (int i = 0; i < 2; i++) {
            int f = tid + 256 * i;
            *(float4*)&Bs[f >> 4][(f & 15) * 4] = pb[i];
        }
        __syncthreads();
        if (t + 1 < nsteps) {
            int k0 = (t + 1) * 32;
            #pragma unroll
            for (int i = 0; i < 4; i++) {
                int f = tid + 256 * i;
                int r = f >> 3, c4 = (f & 7) * 4;
                pa[i] = make_float4(0.f, 0.f, 0.f, 0.f);
                if (rowBase + r < n)
                    pa[i] = *(const float4*)&A[(size_t)(rowBase + r) * K + k0 + c4];
            }
            #pragma unroll
            for (int i = 0; i < 2; i++) {
                int f = tid + 256 * i;
                int r = f >> 4, c4 = (f & 15) * 4;
                pb[i] = *(const float4*)&B[(size_t)(k0 + r) * M + colBase + c4];
            }
        }
        #pragma unroll
        for (int kk = 0; kk < 4; kk++) {
            int kb = kk * 8 + qc;
            uint32_t ah[2][4], al[2][4], bh[4][2], bl[4][2];
            #pragma unroll
            for (int mt = 0; mt < 2; mt++) {
                int r0 = warpM + mt * 16 + qr;
                split_tf32(As[r0][kb],         ah[mt][0], al[mt][0]);
                split_tf32(As[r0 + 8][kb],     ah[mt][1], al[mt][1]);
                split_tf32(As[r0][kb + 4],     ah[mt][2], al[mt][2]);
                split_tf32(As[r0 + 8][kb + 4], ah[mt][3], al[mt][3]);
            }
            #pragma unroll
            for (int nt = 0; nt < 4; nt++) {
                int nn = warpN + nt * 8 + qr;
                split_tf32(Bs[kb][nn],     bh[nt][0], bl[nt][0]);
                split_tf32(Bs[kb + 4][nn], bh[nt][1], bl[nt][1]);
            }
            #pragma unroll
            for (int mt = 0; mt < 2; mt++)
                #pragma unroll
                for (int nt = 0; nt < 4; nt++) {
                    mma8(acc[mt][nt], ah[mt], bl[nt]);
                    mma8(acc[mt][nt], al[mt], bh[nt]);
                    mma8(acc[mt][nt], ah[mt], bh[nt]);
                }
        }
        __syncthreads();
    }

    // ---- epilogue 1: store C (fp32) + fp16 copy ----
    #pragma unroll
    for (int mt = 0; mt < 2; mt++) {
        int r0 = rowBase + warpM + mt * 16 + qr;
        #pragma unroll
        for (int nt = 0; nt < 4; nt++) {
            int cc = colBase + warpN + nt * 8 + qc * 2;
            if (r0 < n) {
                *(float2*)&C[(size_t)r0 * M + cc] = make_float2(acc[mt][nt][0], acc[mt][nt][1]);
                Ch[(size_t)r0 * Mh + (cc >> 1)] = __floats2half2_rn(acc[mt][nt][0], acc[mt][nt][1]);
            }
            if (r0 + 8 < n) {
                *(float2*)&C[(size_t)(r0 + 8) * M + cc] = make_float2(acc[mt][nt][2], acc[mt][nt][3]);
                Ch[(size_t)(r0 + 8) * Mh + (cc >> 1)] = __floats2half2_rn(acc[mt][nt][2], acc[mt][nt][3]);
            }
        }
    }

    // ---- epilogue 2: fused attention logits (fp32-exact) ----
    float psum[4] = {0.f, 0.f, 0.f, 0.f};
    float pdsum[4] = {0.f, 0.f, 0.f, 0.f};
    #pragma unroll
    for (int mt = 0; mt < 2; mt++)
        #pragma unroll
        for (int nt = 0; nt < 4; nt++) {
            int cl = warpN + nt * 8 + qc * 2;
            float as0 = s_as[cl], as1 = s_as[cl + 1];
            float ad0 = s_ad[cl], ad1 = s_ad[cl + 1];
            psum [mt * 2 + 0] += acc[mt][nt][0] * as0 + acc[mt][nt][1] * as1;
            pdsum[mt * 2 + 0] += acc[mt][nt][0] * ad0 + acc[mt][nt][1] * ad1;
            psum [mt * 2 + 1] += acc[mt][nt][2] * as0 + acc[mt][nt][3] * as1;
            pdsum[mt * 2 + 1] += acc[mt][nt][2] * ad0 + acc[mt][nt][3] * ad1;
        }
    #pragma unroll
    for (int off = 1; off <= 2; off <<= 1)
        #pragma unroll
        for (int j = 0; j < 4; j++) {
            psum[j]  += __shfl_xor_sync(0xffffffffu, psum[j],  off);
            pdsum[j] += __shfl_xor_sync(0xffffffffu, pdsum[j], off);
        }
    float* red_s = &As[0][0];
    float* red_d = &As[0][0] + 128;
    __syncthreads();
    if ((warp & 1) == 0 && qc == 0) {
        #pragma unroll
        for (int j = 0; j < 4; j++) {
            int row = warpM + (j >> 1) * 16 + (j & 1) * 8 + qr;
            red_s[row] = psum[j];
            red_d[row] = pdsum[j];
        }
    }
    __syncthreads();
    if ((warp & 1) == 1 && qc == 0) {
        #pragma unroll
        for (int j = 0; j < 4; j++) {
            int row = warpM + (j >> 1) * 16 + (j & 1) * 8 + qr;
            int grow = rowBase + row;
            if (grow < n) {
                out_s[(size_t)grow * lstride + head] = red_s[row] + psum[j];
                out_d[(size_t)grow * lstride + head] = red_d[row] + pdsum[j];
            }
        }
    }
}

__global__ void sgemm1_kernel(const float* __restrict__ A, const float* __restrict__ B,
                              const float* __restrict__ att_s, const float* __restrict__ att_d,
                              int n) {
    tf32_gemm_body(A, B, g_h1, g_h1h, n, 128, 128, att_s, att_d, g_a1s, g_a1d, 2);
}
__global__ void sgemm2_kernel(const float* __restrict__ B,
                              const float* __restrict__ att_s, const float* __restrict__ att_d,
                              int n) {
    tf32_gemm_body(g_hmid, B, g_h2, g_h2h, n, 128, 64, att_s, att_d, g_a2s, g_a2d, 1);
}

// ---------------- layer1 gather: fp16 payload, fp32 accumulate ----------------
__global__ void gather1_kernel(const float* __restrict__ b1, int n) {
    int w = (blockIdx.x * blockDim.x + threadIdx.x) >> 5;
    if (w >= n) return;
    int lane = threadIdx.x & 31;
    int c0 = lane * 4;                     // 4 channels per lane
    float a1d0 = g_a1d[2 * w], a1d1 = g_a1d[2 * w + 1];
    float ws0 = __expf(lrelu(g_a1s[2 * w]     + a1d0));
    float ws1 = __expf(lrelu(g_a1s[2 * w + 1] + a1d1));
    // self loop from fp16 copy (consistent quantization)
    uint2 us = *(const uint2*)&g_h1h[(size_t)w * 64 + lane * 2];
    float2 f0 = __half22float2(*reinterpret_cast<__half2*>(&us.x));
    float2 f1 = __half22float2(*reinterpret_cast<__half2*>(&us.y));
    float wws = (c0 < 64) ? ws0 : ws1;
    float4 acc = make_float4(f0.x * wws, f0.y * wws, f1.x * wws, f1.y * wws);
    float den0 = (lane == 0) ? ws0 : 0.f;
    float den1 = (lane == 0) ? ws1 : 0.f;
    int start = g_ptr[w], end = g_ptr[w + 1];
    for (int base = start; base < end; base += 32) {
        int j = base + lane;
        int s = 0; float e0 = 0.f, e1 = 0.f;
        if (j < end) {
            s = g_ssrc[j];
            float2 as = *(const float2*)&g_a1s[2 * s];
            e0 = __expf(lrelu(as.x + a1d0));
            e1 = __expf(lrelu(as.y + a1d1));
        }
        den0 += e0; den1 += e1;
        int m = min(32, end - base);
        for (int k = 0; k < m; k++) {
            int   sk  = __shfl_sync(0xffffffffu, s, k);
            float w0k = __shfl_sync(0xffffffffu, e0, k);
            float w1k = __shfl_sync(0xffffffffu, e1, k);
            uint2 u = *(const uint2*)&g_h1h[(size_t)sk * 64 + lane * 2];
            float2 h0 = __half22float2(*reinterpret_cast<__half2*>(&u.x));
            float2 h1 = __half22float2(*reinterpret_cast<__half2*>(&u.y));
            float ww = (c0 < 64) ? w0k : w1k;
            acc.x += h0.x * ww; acc.y += h0.y * ww; acc.z += h1.x * ww; acc.w += h1.y * ww;
        }
    }
    #pragma unroll
    for (int off = 16; off >= 1; off >>= 1) {
        den0 += __shfl_xor_sync(0xffffffffu, den0, off);
        den1 += __shfl_xor_sync(0xffffffffu, den1, off);
    }
    float r = 1.0f / (((c0 < 64) ? den0 : den1) + EPSQ);
    float4 o;
    o.x = elu1(acc.x * r + b1[c0]);
    o.y = elu1(acc.y * r + b1[c0 + 1]);
    o.z = elu1(acc.z * r + b1[c0 + 2]);
    o.w = elu1(acc.w * r + b1[c0 + 3]);
    *(float4*)&g_hmid[(size_t)w * 128 + c0] = o;
}

// ---------------- layer2 gather: fp16 payload, fp32 accumulate ----------------
__global__ void gather2_kernel(const float* __restrict__ b2, int n) {
    int w = (blockIdx.x * blockDim.x + threadIdx.x) >> 5;
    if (w >= n) return;
    int lane = threadIdx.x & 31;
    int c0 = lane * 2;
    float a2d = g_a2d[w];
    float ws0 = __expf(lrelu(g_a2s[w] + a2d));
    float2 hs = __half22float2(g_h2h[(size_t)w * 32 + lane]);
    float2 acc = make_float2(hs.x * ws0, hs.y * ws0);
    float den = (lane == 0) ? ws0 : 0.f;
    int start = g_ptr[w], end = g_ptr[w + 1];
    for (int base = start; base < end; base += 32) {
        int j = base + lane;
        int s = 0; float e0 = 0.f;
        if (j < end) {
            s = g_ssrc[j];
            e0 = __expf(lrelu(g_a2s[s] + a2d));
        }
        den += e0;
        int m = min(32, end - base);
        for (int k = 0; k < m; k++) {
            int   sk  = __shfl_sync(0xffffffffu, s, k);
            float w0k = __shfl_sync(0xffffffffu, e0, k);
            float2 h = __half22float2(g_h2h[(size_t)sk * 32 + lane]);
            acc.x += h.x * w0k; acc.y += h.y * w0k;
        }
    }
    #pragma unroll
    for (int off = 16; off >= 1; off >>= 1)
        den += __shfl_xor_sync(0xffffffffu, den, off);
    float r = 1.0f / (den + EPSQ);
    float2 o;
    o.x = elu1(acc.x * r + b2[c0]);
    o.y = elu1(acc.y * r + b2[c0 + 1]);
    *(float2*)&g_hout[(size_t)w * 64 + c0] = o;
}

// ---------------- final: @ lin_w + lin_b, sigmoid ----------------
__global__ void final_kernel(const float* __restrict__ lin_w, const float* __restrict__ lin_b,
                             float* __restrict__ out, int n) {
    __shared__ float sw[64 * 16];
    __shared__ float st[16][66];
    int tid = threadIdx.x;
    int nb = blockIdx.x * 16;
    #pragma unroll
    for (int i = 0; i < 4; i++) sw[tid + 256 * i] = lin_w[tid + 256 * i];
    #pragma unroll
    for (int i = 0; i < 4; i++) {
        int id = tid + 256 * i;
        int g = id >> 6;
        int c = id & 63;
        int node = nb + g;
        st[g][c] = (node < n) ? g_hout[(size_t)node * 64 + c] : 0.f;
    }
    __syncthreads();
    int g = tid >> 4;
    int o = tid & 15;
    int node = nb + g;
    if (node >= n) return;
    float acc = lin_b[o];
    #pragma unroll
    for (int c = 0; c < 64; c++)
        acc += st[g][c] * sw[c * 16 + o];
    out[(size_t)node * 16 + o] = 1.0f / (1.0f + __expf(-acc));
}

// ---------------- launcher ----------------
extern "C" void kernel_launch(void* const* d_in, const int* in_sizes, int n_in,
                              void* d_out, int out_size) {
    const float* x        = (const float*)d_in[0];
    const void*  ei       = d_in[1];
    const float* W1       = (const float*)d_in[2];
    const float* att_src1 = (const float*)d_in[3];
    const float* att_dst1 = (const float*)d_in[4];
    const float* b1       = (const float*)d_in[5];
    const float* W2       = (const float*)d_in[6];
    const float* att_src2 = (const float*)d_in[7];
    const float* att_dst2 = (const float*)d_in[8];
    const float* b2       = (const float*)d_in[9];
    const float* lin_w    = (const float*)d_in[10];
    const float* lin_b    = (const float*)d_in[11];
    float*       out      = (float*)d_out;

    int n = in_sizes[0] / 128;        // 50000
    int E = in_sizes[1] / 2;          // 800000
    int nblk = (n + 1023) / 1024;     // 49 scan tiles
    int gy   = (n + 127) / 128;       // 391 gemm row tiles

    // CSR build (shared by both layers)
    detect_kernel <<<1, 256>>>(ei, E, n);
    zero_kernel   <<<(n + 4 + 255) / 256, 256>>>(n);
    convert_kernel<<<(E + 255) / 256, 256>>>(ei, E);
    scanA_kernel  <<<nblk, 256>>>(n);
    scanB_kernel  <<<1, 64>>>(nblk);
    scanC_kernel  <<<nblk, 256>>>(n);
    scatter_kernel<<<(E + 255) / 256, 256>>>(E);

    // layer 1 (logits fused into GEMM epilogue)
    sgemm1_kernel <<<dim3(2, gy), 256>>>(x, W1, att_src1, att_dst1, n);
    gather1_kernel<<<(n + 7) / 8, 256>>>(b1, n);
    // layer 2
    sgemm2_kernel <<<dim3(1, gy), 256>>>(W2, att_src2, att_dst2, n);
    gather2_kernel<<<(n + 7) / 8, 256>>>(b2, n);
    // head
    final_kernel  <<<(n + 15) / 16, 256>>>(lin_w, lin_b, out, n);
}

// round 11
// speedup vs baseline: 2.7402x; 1.0945x over previous
#include <cuda_runtime.h>
#include <cuda_bf16.h>
#include <cuda_fp16.h>
#include <cstdint>

#define NN 50000
#define EE 800000
#define EPSQ 1e-16f

// ---------------- scratch (static device globals; no allocation) ----------------
__device__ __half2 g_h1h [NN * 64];    // layer1 GEMM out, fp16 (256B/row)
__device__ float   g_a1s [NN * 2];
__device__ float   g_a1d [NN * 2];
__device__ float   g_hmid[NN * 128];   // layer1 final -> layer2 GEMM input (fp32)
__device__ __half2 g_h2h [NN * 32];    // layer2 GEMM out, fp16 (128B/row)
__device__ float   g_a2s [NN];
__device__ float   g_a2d [NN];
__device__ float   g_hout[NN * 64];    // layer2 final
__device__ int     g_src [EE];
__device__ int     g_dst [EE];
__device__ int     g_deg [NN + 4];
__device__ int     g_ptr [NN + 8];
__device__ int     g_pos [NN + 8];
__device__ int2    g_sedge[EE];        // (src,dst) sorted by dst
__device__ float2  g_ew1 [EE];         // per-edge softmax weights, layer1 (2 heads)
__device__ float   g_ew2 [EE];         // layer2
__device__ int     g_bsum[64];
__device__ int     g_boff[64];
__device__ int     g_e64;

__device__ __forceinline__ float lrelu(float x) { return x > 0.f ? x : 0.2f * x; }
__device__ __forceinline__ float elu1(float x)  { return x > 0.f ? x : expm1f(x); }

// ---------------- fused: edge dtype detect (block 0) + zero degree ----------------
__global__ void detzero_kernel(const void* ei, int E, int n) {
    int i = blockIdx.x * blockDim.x + threadIdx.x;
    if (i < n + 4) g_deg[i] = 0;
    if (blockIdx.x == 0) {
        __shared__ int ok;
        if (threadIdx.x == 0) ok = 1;
        __syncthreads();
        int stride = E > 256 ? E / 256 : 1;
        long long idx = (long long)threadIdx.x * stride;
        if (idx < E) {
            long long v = ((const long long*)ei)[idx];
            if (v < 0 || v >= n) ok = 0;
        }
        __syncthreads();
        if (threadIdx.x == 0) g_e64 = ok;
    }
}

// ---------------- convert + degree histogram ----------------
__global__ void convert_kernel(const void* ei, int E) {
    int e = blockIdx.x * blockDim.x + threadIdx.x;
    if (e >= E) return;
    int s, d;
    if (g_e64) {
        const long long* p = (const long long*)ei;
        s = (int)p[e];
        d = (int)p[E + e];
    } else {
        const int* p = (const int*)ei;
        s = p[e];
        d = p[E + e];
    }
    g_src[e] = s;
    g_dst[e] = d;
    atomicAdd(&g_deg[d], 1);
}

// ---------------- 3-phase parallel exclusive scan ----------------
__global__ void scanA_kernel(int n) {
    int b = blockIdx.x;
    int base = b * 1024 + threadIdx.x * 4;
    int s = 0;
    if (base < n) {
        int4 v = *(const int4*)&g_deg[base];
        s = v.x + ((base + 1 < n) ? v.y : 0) + ((base + 2 < n) ? v.z : 0) + ((base + 3 < n) ? v.w : 0);
    }
    int lane = threadIdx.x & 31, wid = threadIdx.x >> 5;
    #pragma unroll
    for (int off = 16; off >= 1; off >>= 1) s += __shfl_xor_sync(0xffffffffu, s, off);
    __shared__ int ws[8];
    if (lane == 0) ws[wid] = s;
    __syncthreads();
    if (threadIdx.x == 0) {
        int t = 0;
        #pragma unroll
        for (int i = 0; i < 8; i++) t += ws[i];
        g_bsum[b] = t;
    }
}

__global__ void scanB_kernel(int nb) {
    int tid = threadIdx.x;
    int lane = tid & 31, w = tid >> 5;
    int v = (tid < nb) ? g_bsum[tid] : 0;
    int inc = v;
    #pragma unroll
    for (int off = 1; off < 32; off <<= 1) {
        int t = __shfl_up_sync(0xffffffffu, inc, off);
        if (lane >= off) inc += t;
    }
    __shared__ int wt[2];
    if (lane == 31) wt[w] = inc;
    __syncthreads();
    if (w == 1) inc += wt[0];
    g_boff[tid] = inc - v;
}

__global__ void scanC_kernel(int n) {
    int b = blockIdx.x;
    int idx0 = b * 1024 + threadIdx.x * 4;
    int d0 = 0, d1 = 0, d2 = 0, d3 = 0;
    if (idx0 < n) {
        int4 v = *(const int4*)&g_deg[idx0];
        d0 = v.x;
        d1 = (idx0 + 1 < n) ? v.y : 0;
        d2 = (idx0 + 2 < n) ? v.z : 0;
        d3 = (idx0 + 3 < n) ? v.w : 0;
    }
    int tsum = d0 + d1 + d2 + d3;
    int lane = threadIdx.x & 31, wid = threadIdx.x >> 5;
    int inc = tsum;
    #pragma unroll
    for (int off = 1; off < 32; off <<= 1) {
        int t = __shfl_up_sync(0xffffffffu, inc, off);
        if (lane >= off) inc += t;
    }
    __shared__ int ws[8];
    if (lane == 31) ws[wid] = inc;
    __syncthreads();
    __shared__ int wo[8];
    if (threadIdx.x == 0) {
        int run = 0;
        #pragma unroll
        for (int i = 0; i < 8; i++) { wo[i] = run; run += ws[i]; }
    }
    __syncthreads();
    int base = g_boff[b] + wo[wid] + (inc - tsum);
    int p0 = base, p1 = base + d0, p2 = p1 + d1, p3 = p2 + d2;
    if (idx0 < n) {
        if (idx0 + 3 < n) {
            *(int4*)&g_ptr[idx0] = make_int4(p0, p1, p2, p3);
            *(int4*)&g_pos[idx0] = make_int4(p0, p1, p2, p3);
        } else {
            int pv[4] = {p0, p1, p2, p3};
            for (int i = 0; i < 4 && idx0 + i < n; i++) {
                g_ptr[idx0 + i] = pv[i];
                g_pos[idx0 + i] = pv[i];
            }
        }
        if (idx0 <= n - 1 && n - 1 < idx0 + 4) {
            int pv[4] = {p0, p1, p2, p3};
            int dv[4] = {d0, d1, d2, d3};
            int k = (n - 1) - idx0;
            g_ptr[n] = pv[k] + dv[k];
        }
    }
}

// ---------------- scatter (src,dst) into dst-sorted order ----------------
__global__ void scatter_kernel(int E) {
    int e = blockIdx.x * blockDim.x + threadIdx.x;
    if (e >= E) return;
    int d = g_dst[e];
    int p = atomicAdd(&g_pos[d], 1);
    g_sedge[p] = make_int2(g_src[e], d);
}

// ---------------- per-edge softmax weights (CSR order, lane per edge) ----------------
__global__ void edgew1_kernel(int E) {
    int j = blockIdx.x * blockDim.x + threadIdx.x;
    if (j >= E) return;
    int2 e = g_sedge[j];
    float2 as = *(const float2*)&g_a1s[2 * e.x];
    float2 ad = *(const float2*)&g_a1d[2 * e.y];
    g_ew1[j] = make_float2(__expf(lrelu(as.x + ad.x)), __expf(lrelu(as.y + ad.y)));
}

__global__ void edgew2_kernel(int E) {
    int j = blockIdx.x * blockDim.x + threadIdx.x;
    if (j >= E) return;
    int2 e = g_sedge[j];
    g_ew2[j] = __expf(lrelu(g_a2s[e.x] + g_a2d[e.y]));
}

// ---------------- 3xTF32 tensor-core GEMM + fused logits + fp16 output ----------------
__device__ __forceinline__ void split_tf32(float x, uint32_t& hi, uint32_t& lo) {
    uint32_t h;
    asm("cvt.rna.tf32.f32 %0, %1;" : "=r"(h) : "f"(x));
    hi = h;
    lo = __float_as_uint(x - __uint_as_float(h));
}

__device__ __forceinline__ void mma8(float* c, const uint32_t* a, const uint32_t* b) {
    asm volatile(
        "mma.sync.aligned.m16n8k8.row.col.f32.tf32.tf32.f32 "
        "{%0,%1,%2,%3}, {%4,%5,%6,%7}, {%8,%9}, {%0,%1,%2,%3};"
        : "+f"(c[0]), "+f"(c[1]), "+f"(c[2]), "+f"(c[3])
        : "r"(a[0]), "r"(a[1]), "r"(a[2]), "r"(a[3]), "r"(b[0]), "r"(b[1]));
}

__device__ __forceinline__ void tf32_gemm_body(const float* __restrict__ A,
                                               const float* __restrict__ B,
                                               __half2* __restrict__ Ch,   // fp16 output, M/2 per row
                                               int n, int K, int M,
                                               const float* __restrict__ att_s,
                                               const float* __restrict__ att_d,
                                               float* __restrict__ out_s,
                                               float* __restrict__ out_d,
                                               int lstride) {
    __shared__ float As[128][36];
    __shared__ float Bs[32][68];
    __shared__ float s_as[64], s_ad[64];
    int tid  = threadIdx.x;
    int warp = tid >> 5, lane = tid & 31;
    int qr = lane >> 2, qc = lane & 3;
    int warpM = (warp >> 1) * 32;
    int warpN = (warp & 1) * 32;
    int rowBase = blockIdx.y * 128;
    int colBase = blockIdx.x * 64;
    int head    = blockIdx.x;
    int Mh      = M >> 1;

    if (tid < 64) {
        s_as[tid] = att_s[head * 64 + tid];
        s_ad[tid] = att_d[head * 64 + tid];
    }

    float acc[2][4][4];
    #pragma unroll
    for (int mt = 0; mt < 2; mt++)
        #pragma unroll
        for (int nt = 0; nt < 4; nt++)
            #pragma unroll
            for (int i = 0; i < 4; i++) acc[mt][nt][i] = 0.f;

    float4 pa[4], pb[2];
    #pragma unroll
    for (int i = 0; i < 4; i++) {
        int f = tid + 256 * i;
        int r = f >> 3, c4 = (f & 7) * 4;
        pa[i] = make_float4(0.f, 0.f, 0.f, 0.f);
        if (rowBase + r < n)
            pa[i] = *(const float4*)&A[(size_t)(rowBase + r) * K + c4];
    }
    #pragma unroll
    for (int i = 0; i < 2; i++) {
        int f = tid + 256 * i;
        int r = f >> 4, c4 = (f & 15) * 4;
        pb[i] = *(const float4*)&B[(size_t)r * M + colBase + c4];
    }

    int nsteps = K >> 5;
    for (int t = 0; t < nsteps; t++) {
        #pragma unroll
        for (int i = 0; i < 4; i++) {
            int f = tid + 256 * i;
            *(float4*)&As[f >> 3][(f & 7) * 4] = pa[i];
        }
        #pragma unroll
        for (int i = 0; i < 2; i++) {
            int f = tid + 256 * i;
            *(float4*)&Bs[f >> 4][(f & 15) * 4] = pb[i];
        }
        __syncthreads();
        if (t + 1 < nsteps) {
            int k0 = (t + 1) * 32;
            #pragma unroll
            for (int i = 0; i < 4; i++) {
                int f = tid + 256 * i;
                int r = f >> 3, c4 = (f & 7) * 4;
                pa[i] = make_float4(0.f, 0.f, 0.f, 0.f);
                if (rowBase + r < n)
                    pa[i] = *(const float4*)&A[(size_t)(rowBase + r) * K + k0 + c4];
            }
            #pragma unroll
            for (int i = 0; i < 2; i++) {
                int f = tid + 256 * i;
                int r = f >> 4, c4 = (f & 15) * 4;
                pb[i] = *(const float4*)&B[(size_t)(k0 + r) * M + colBase + c4];
            }
        }
        #pragma unroll
        for (int kk = 0; kk < 4; kk++) {
            int kb = kk * 8 + qc;
            uint32_t ah[2][4], al[2][4], bh[4][2], bl[4][2];
            #pragma unroll
            for (int mt = 0; mt < 2; mt++) {
                int r0 = warpM + mt * 16 + qr;
                split_tf32(As[r0][kb],         ah[mt][0], al[mt][0]);
                split_tf32(As[r0 + 8][kb],     ah[mt][1], al[mt][1]);
                split_tf32(As[r0][kb + 4],     ah[mt][2], al[mt][2]);
                split_tf32(As[r0 + 8][kb + 4], ah[mt][3], al[mt][3]);
            }
            #pragma unroll
            for (int nt = 0; nt < 4; nt++) {
                int nn = warpN + nt * 8 + qr;
                split_tf32(Bs[kb][nn],     bh[nt][0], bl[nt][0]);
                split_tf32(Bs[kb + 4][nn], bh[nt][1], bl[nt][1]);
            }
            #pragma unroll
            for (int mt = 0; mt < 2; mt++)
                #pragma unroll
                for (int nt = 0; nt < 4; nt++) {
                    mma8(acc[mt][nt], ah[mt], bl[nt]);
                    mma8(acc[mt][nt], al[mt], bh[nt]);
                    mma8(acc[mt][nt], ah[mt], bh[nt]);
                }
        }
        __syncthreads();
    }

    // ---- epilogue 1: fp16 output only (fp32 C is dead downstream) ----
    #pragma unroll
    for (int mt = 0; mt < 2; mt++) {
        int r0 = rowBase + warpM + mt * 16 + qr;
        #pragma unroll
        for (int nt = 0; nt < 4; nt++) {
            int cc = colBase + warpN + nt * 8 + qc * 2;
            if (r0 < n)
                Ch[(size_t)r0 * Mh + (cc >> 1)] = __floats2half2_rn(acc[mt][nt][0], acc[mt][nt][1]);
            if (r0 + 8 < n)
                Ch[(size_t)(r0 + 8) * Mh + (cc >> 1)] = __floats2half2_rn(acc[mt][nt][2], acc[mt][nt][3]);
        }
    }

    // ---- epilogue 2: fused attention logits (fp32-exact) ----
    float psum[4] = {0.f, 0.f, 0.f, 0.f};
    float pdsum[4] = {0.f, 0.f, 0.f, 0.f};
    #pragma unroll
    for (int mt = 0; mt < 2; mt++)
        #pragma unroll
        for (int nt = 0; nt < 4; nt++) {
            int cl = warpN + nt * 8 + qc * 2;
            float as0 = s_as[cl], as1 = s_as[cl + 1];
            float ad0 = s_ad[cl], ad1 = s_ad[cl + 1];
            psum [mt * 2 + 0] += acc[mt][nt][0] * as0 + acc[mt][nt][1] * as1;
            pdsum[mt * 2 + 0] += acc[mt][nt][0] * ad0 + acc[mt][nt][1] * ad1;
            psum [mt * 2 + 1] += acc[mt][nt][2] * as0 + acc[mt][nt][3] * as1;
            pdsum[mt * 2 + 1] += acc[mt][nt][2] * ad0 + acc[mt][nt][3] * ad1;
        }
    #pragma unroll
    for (int off = 1; off <= 2; off <<= 1)
        #pragma unroll
        for (int j = 0; j < 4; j++) {
            psum[j]  += __shfl_xor_sync(0xffffffffu, psum[j],  off);
            pdsum[j] += __shfl_xor_sync(0xffffffffu, pdsum[j], off);
        }
    float* red_s = &As[0][0];
    float* red_d = &As[0][0] + 128;
    __syncthreads();
    if ((warp & 1) == 0 && qc == 0) {
        #pragma unroll
        for (int j = 0; j < 4; j++) {
            int row = warpM + (j >> 1) * 16 + (j & 1) * 8 + qr;
            red_s[row] = psum[j];
            red_d[row] = pdsum[j];
        }
    }
    __syncthreads();
    if ((warp & 1) == 1 && qc == 0) {
        #pragma unroll
        for (int j = 0; j < 4; j++) {
            int row = warpM + (j >> 1) * 16 + (j & 1) * 8 + qr;
            int grow = rowBase + row;
            if (grow < n) {
                out_s[(size_t)grow * lstride + head] = red_s[row] + psum[j];
                out_d[(size_t)grow * lstride + head] = red_d[row] + pdsum[j];
            }
        }
    }
}

__global__ void sgemm1_kernel(const float* __restrict__ A, const float* __restrict__ B,
                              const float* __restrict__ att_s, const float* __restrict__ att_d,
                              int n) {
    tf32_gemm_body(A, B, g_h1h, n, 128, 128, att_s, att_d, g_a1s, g_a1d, 2);
}
__global__ void sgemm2_kernel(const float* __restrict__ B,
                              const float* __restrict__ att_s, const float* __restrict__ att_d,
                              int n) {
    tf32_gemm_body(g_hmid, B, g_h2h, n, 128, 64, att_s, att_d, g_a2s, g_a2d, 1);
}

// ---------------- layer1 gather: streaming, no shfl ----------------
__global__ void gather1_kernel(const float* __restrict__ b1, int n) {
    int w = (blockIdx.x * blockDim.x + threadIdx.x) >> 5;
    if (w >= n) return;
    int lane = threadIdx.x & 31;
    int c0 = lane * 4;
    // self loop
    float ws0 = __expf(lrelu(g_a1s[2 * w]     + g_a1d[2 * w]));
    float ws1 = __expf(lrelu(g_a1s[2 * w + 1] + g_a1d[2 * w + 1]));
    uint2 us = *(const uint2*)&g_h1h[(size_t)w * 64 + lane * 2];
    float2 f0 = __half22float2(*reinterpret_cast<__half2*>(&us.x));
    float2 f1 = __half22float2(*reinterpret_cast<__half2*>(&us.y));
    float wws = (c0 < 64) ? ws0 : ws1;
    float4 acc = make_float4(f0.x * wws, f0.y * wws, f1.x * wws, f1.y * wws);
    float den0 = ws0, den1 = ws1;          // every lane holds the full sum
    int start = g_ptr[w], end = g_ptr[w + 1];
    #pragma unroll 4
    for (int j = start; j < end; j++) {
        int s = g_sedge[j].x;              // broadcast load (1 sector)
        float2 wv = g_ew1[j];              // broadcast load
        uint2 u = *(const uint2*)&g_h1h[(size_t)s * 64 + lane * 2];
        float2 h0 = __half22float2(*reinterpret_cast<__half2*>(&u.x));
        float2 h1 = __half22float2(*reinterpret_cast<__half2*>(&u.y));
        float ww = (c0 < 64) ? wv.x : wv.y;
        acc.x += h0.x * ww; acc.y += h0.y * ww; acc.z += h1.x * ww; acc.w += h1.y * ww;
        den0 += wv.x; den1 += wv.y;
    }
    float r = 1.0f / (((c0 < 64) ? den0 : den1) + EPSQ);
    float4 o;
    o.x = elu1(acc.x * r + b1[c0]);
    o.y = elu1(acc.y * r + b1[c0 + 1]);
    o.z = elu1(acc.z * r + b1[c0 + 2]);
    o.w = elu1(acc.w * r + b1[c0 + 3]);
    *(float4*)&g_hmid[(size_t)w * 128 + c0] = o;
}

// ---------------- layer2 gather: streaming, no shfl ----------------
__global__ void gather2_kernel(const float* __restrict__ b2, int n) {
    int w = (blockIdx.x * blockDim.x + threadIdx.x) >> 5;
    if (w >= n) return;
    int lane = threadIdx.x & 31;
    int c0 = lane * 2;
    float ws0 = __expf(lrelu(g_a2s[w] + g_a2d[w]));
    float2 hs = __half22float2(g_h2h[(size_t)w * 32 + lane]);
    float2 acc = make_float2(hs.x * ws0, hs.y * ws0);
    float den = ws0;
    int start = g_ptr[w], end = g_ptr[w + 1];
    #pragma unroll 4
    for (int j = start; j < end; j++) {
        int s = g_sedge[j].x;
        float wv = g_ew2[j];
        float2 h = __half22float2(g_h2h[(size_t)s * 32 + lane]);
        acc.x += h.x * wv; acc.y += h.y * wv;
        den += wv;
    }
    float r = 1.0f / (den + EPSQ);
    float2 o;
    o.x = elu1(acc.x * r + b2[c0]);
    o.y = elu1(acc.y * r + b2[c0 + 1]);
    *(float2*)&g_hout[(size_t)w * 64 + c0] = o;
}

// ---------------- final: @ lin_w + lin_b, sigmoid ----------------
__global__ void final_kernel(const float* __restrict__ lin_w, const float* __restrict__ lin_b,
                             float* __restrict__ out, int n) {
    __shared__ float sw[64 * 16];
    __shared__ float st[16][66];
    int tid = threadIdx.x;
    int nb = blockIdx.x * 16;
    #pragma unroll
    for (int i = 0; i < 4; i++) sw[tid + 256 * i] = lin_w[tid + 256 * i];
    #pragma unroll
    for (int i = 0; i < 4; i++) {
        int id = tid + 256 * i;
        int g = id >> 6;
        int c = id & 63;
        int node = nb + g;
        st[g][c] = (node < n) ? g_hout[(size_t)node * 64 + c] : 0.f;
    }
    __syncthreads();
    int g = tid >> 4;
    int o = tid & 15;
    int node = nb + g;
    if (node >= n) return;
    float acc = lin_b[o];
    #pragma unroll
    for (int c = 0; c < 64; c++)
        acc += st[g][c] * sw[c * 16 + o];
    out[(size_t)node * 16 + o] = 1.0f / (1.0f + __expf(-acc));
}

// ---------------- launcher ----------------
extern "C" void kernel_launch(void* const* d_in, const int* in_sizes, int n_in,
                              void* d_out, int out_size) {
    const float* x        = (const float*)d_in[0];
    const void*  ei       = d_in[1];
    const float* W1       = (const float*)d_in[2];
    const float* att_src1 = (const float*)d_in[3];
    const float* att_dst1 = (const float*)d_in[4];
    const float* b1       = (const float*)d_in[5];
    const float* W2       = (const float*)d_in[6];
    const float* att_src2 = (const float*)d_in[7];
    const float* att_dst2 = (const float*)d_in[8];
    const float* b2       = (const float*)d_in[9];
    const float* lin_w    = (const float*)d_in[10];
    const float* lin_b    = (const float*)d_in[11];
    float*       out      = (float*)d_out;

    int n = in_sizes[0] / 128;        // 50000
    int E = in_sizes[1] / 2;          // 800000
    int nblk = (n + 1023) / 1024;     // 49 scan tiles
    int gy   = (n + 127) / 128;       // 391 gemm row tiles

    // CSR build
    detzero_kernel<<<(n + 4 + 255) / 256, 256>>>(ei, E, n);
    convert_kernel<<<(E + 255) / 256, 256>>>(ei, E);
    scanA_kernel  <<<nblk, 256>>>(n);
    scanB_kernel  <<<1, 64>>>(nblk);
    scanC_kernel  <<<nblk, 256>>>(n);
    scatter_kernel<<<(E + 255) / 256, 256>>>(E);

    // layer 1
    sgemm1_kernel <<<dim3(2, gy), 256>>>(x, W1, att_src1, att_dst1, n);
    edgew1_kernel <<<(E + 255) / 256, 256>>>(E);
    gather1_kernel<<<(n + 7) / 8, 256>>>(b1, n);
    // layer 2
    sgemm2_kernel <<<dim3(1, gy), 256>>>(W2, att_src2, att_dst2, n);
    edgew2_kernel <<<(E + 255) / 256, 256>>>(E);
    gather2_kernel<<<(n + 7) / 8, 256>>>(b2, n);
    // head
    final_kernel  <<<(n + 15) / 16, 256>>>(lin_w, lin_b, out, n);
}